// round 3
// baseline (speedup 1.0000x reference)
#include <cuda_runtime.h>
#include <cuda_bf16.h>
#include <cstdint>

#define B_    2
#define H_    16
#define S_    2048
#define D_    64
#define QT    128          // q rows per CTA
#define KC    64           // k cols per chunk
#define NCH   (S_/KC)      // 32 chunks
#define NTHR  256
#define SCALEF 0.125f      // 1/sqrt(64)
#define MWORDS (B_ * S_ * S_ / 32)   // 262144 packed mask words
#define MW_ROW (S_ / 32)             // 64 words per row

// ---------------------------------------------------------------------------
// Globals: packed mask bits (1 MB) + detected dtype mode
// ---------------------------------------------------------------------------
__device__ unsigned g_mask_bits[MWORDS];
__device__ int g_mode;   // 0 = 1-byte bool, 1 = 4-byte (int32/float32)

// ---------------------------------------------------------------------------
// Mask dtype detection: scan first 4096 words of the raw buffer.
//  - float32 mask: words are 0x00000000 / 0x3F800000
//  - int32 mask:   words are 0 / 1
//  - u8 bool mask: words are 4 packed bytes each 0/1 -> values like 0x01000101
// ---------------------------------------------------------------------------
__global__ void detect_kernel(const unsigned* __restrict__ m) {
    __shared__ int s_other;
    if (threadIdx.x == 0) s_other = 0;
    __syncthreads();
    int other = 0;
    for (int i = threadIdx.x; i < 4096; i += 256) {
        unsigned w = m[i];
        if (w != 0u && w != 1u && w != 0x3F800000u) other++;
    }
    atomicAdd(&s_other, other);
    __syncthreads();
    if (threadIdx.x == 0) g_mode = (s_other > 0) ? 0 : 1;
}

__device__ __forceinline__ unsigned pk4nz(unsigned v) {
    // 4 bytes (any nonzero = true) -> 4 bits
    unsigned b = __vminu4(v, 0x01010101u);      // each byte -> 0/1
    return (b | (b >> 7) | (b >> 14) | (b >> 21)) & 0xFu;
}

// Pack mask into bits: word w covers elements [32w, 32w+32)
__global__ void pack_kernel(const unsigned char* __restrict__ m8) {
    int w = blockIdx.x * blockDim.x + threadIdx.x;
    if (w >= MWORDS) return;
    unsigned bits = 0;
    if (g_mode == 0) {
        const uint4* p = (const uint4*)(m8 + (size_t)w * 32);
        uint4 u0 = p[0], u1 = p[1];
        bits = pk4nz(u0.x) | (pk4nz(u0.y) << 4) | (pk4nz(u0.z) << 8) | (pk4nz(u0.w) << 12)
             | (pk4nz(u1.x) << 16) | (pk4nz(u1.y) << 20) | (pk4nz(u1.z) << 24) | (pk4nz(u1.w) << 28);
    } else {
        const uint4* p = (const uint4*)m8 + (size_t)w * 8;
        #pragma unroll
        for (int j = 0; j < 8; j++) {
            uint4 u = p[j];
            bits |= ((unsigned)(u.x != 0u) << (4 * j))
                  | ((unsigned)(u.y != 0u) << (4 * j + 1))
                  | ((unsigned)(u.z != 0u) << (4 * j + 2))
                  | ((unsigned)(u.w != 0u) << (4 * j + 3));
        }
    }
    g_mask_bits[w] = bits;
}

// ---------------------------------------------------------------------------
// Shared memory
// ---------------------------------------------------------------------------
struct __align__(16) Smem {
    union {
        float qstage[QT][D_];                 // 32 KB (Q staging, start only)
        struct {
            unsigned short khi[KC][D_ + 4];   // bf16 bits, padded stride 68
            unsigned short klo[KC][D_ + 4];
            unsigned short vthi[D_][KC + 4];  // V transposed: [d][k]
            unsigned short vtlo[D_][KC + 4];
        } kv;
    };
};

// ---------------------------------------------------------------------------
// Helpers
// ---------------------------------------------------------------------------
__device__ __forceinline__ void splitf(float x, unsigned short& hi, unsigned short& lo) {
    __nv_bfloat16 h = __float2bfloat16_rn(x);
    hi = __bfloat16_as_ushort(h);
    lo = __bfloat16_as_ushort(__float2bfloat16_rn(x - __bfloat162float(h)));
}

__device__ __forceinline__ void split2(float a, float b, unsigned& hi, unsigned& lo) {
    unsigned short ah, al, bh, bl;
    splitf(a, ah, al);
    splitf(b, bh, bl);
    hi = (unsigned)ah | ((unsigned)bh << 16);
    lo = (unsigned)al | ((unsigned)bl << 16);
}

__device__ __forceinline__ void mma16816(float* c, const unsigned* a, unsigned b0, unsigned b1) {
    asm volatile(
        "mma.sync.aligned.m16n8k16.row.col.f32.bf16.bf16.f32 "
        "{%0,%1,%2,%3}, {%4,%5,%6,%7}, {%8,%9}, {%0,%1,%2,%3};"
        : "+f"(c[0]), "+f"(c[1]), "+f"(c[2]), "+f"(c[3])
        : "r"(a[0]), "r"(a[1]), "r"(a[2]), "r"(a[3]), "r"(b0), "r"(b1));
}

__device__ __forceinline__ void load_kv(Smem* sm, const float* Kb, const float* Vb,
                                        int kc, int tid, bool withV) {
    const float* Kc = Kb + (size_t)kc * KC * D_;
    #pragma unroll
    for (int i = tid; i < KC * D_ / 4; i += NTHR) {
        int r = i >> 4, c = (i & 15) << 2;
        float4 v = *(const float4*)(Kc + r * D_ + c);
        unsigned short h, l;
        splitf(v.x, h, l); sm->kv.khi[r][c + 0] = h; sm->kv.klo[r][c + 0] = l;
        splitf(v.y, h, l); sm->kv.khi[r][c + 1] = h; sm->kv.klo[r][c + 1] = l;
        splitf(v.z, h, l); sm->kv.khi[r][c + 2] = h; sm->kv.klo[r][c + 2] = l;
        splitf(v.w, h, l); sm->kv.khi[r][c + 3] = h; sm->kv.klo[r][c + 3] = l;
    }
    if (withV) {
        const float* Vc = Vb + (size_t)kc * KC * D_;
        #pragma unroll
        for (int i = tid; i < KC * D_ / 4; i += NTHR) {
            int r = i >> 4, c = (i & 15) << 2;
            float4 v = *(const float4*)(Vc + r * D_ + c);
            unsigned short h, l;
            splitf(v.x, h, l); sm->kv.vthi[c + 0][r] = h; sm->kv.vtlo[c + 0][r] = l;
            splitf(v.y, h, l); sm->kv.vthi[c + 1][r] = h; sm->kv.vtlo[c + 1][r] = l;
            splitf(v.z, h, l); sm->kv.vthi[c + 2][r] = h; sm->kv.vtlo[c + 2][r] = l;
            splitf(v.w, h, l); sm->kv.vthi[c + 3][r] = h; sm->kv.vtlo[c + 3][r] = l;
        }
    }
}

// ---------------------------------------------------------------------------
// Kernel: one CTA = 128 q-rows of one (b,h). 8 warps, warp owns 16 rows.
// Sweep 1: full-precision scores -> row max m, denom l.
// Sweep 2: same scores, write p = exp(s-m)/l, accumulate O += P@V.
// ---------------------------------------------------------------------------
__global__ void __launch_bounds__(NTHR, 1)
sdpa_kernel(const float* __restrict__ Q, const float* __restrict__ K,
            const float* __restrict__ V, float* __restrict__ out) {
    __shared__ Smem sm;
    const int tid  = threadIdx.x;
    const int w    = tid >> 5;
    const int lane = tid & 31;
    const int gid  = lane >> 2;    // group (row) id 0..7
    const int tig  = lane & 3;     // thread-in-group 0..3
    const int b    = blockIdx.z, h = blockIdx.y;
    const int q0   = blockIdx.x * QT;

    const size_t bh = (size_t)b * H_ + h;
    const float* Qb = Q + (bh * S_ + q0) * D_;
    const float* Kb = K + bh * S_ * D_;
    const float* Vb = V + bh * S_ * D_;
    float* ctx  = out + (bh * S_ + q0) * D_;
    float* attn = out + (size_t)B_ * H_ * S_ * D_ + (bh * S_ + q0) * S_;

    // ---- stage Q and build per-warp A fragments (bf16 hi/lo, resident) ----
    #pragma unroll
    for (int i = tid; i < QT * D_ / 4; i += NTHR) {
        int r = i >> 4, c = (i & 15) << 2;
        *(float4*)&sm.qstage[r][c] = *(const float4*)(Qb + r * D_ + c);
    }
    __syncthreads();

    const int qr0 = w * 16 + gid;            // local row for c0,c1 accums
    unsigned qhi[4][4], qlo[4][4];
    #pragma unroll
    for (int kb = 0; kb < 4; kb++) {
        int c0 = kb * 16 + 2 * tig;
        split2(sm.qstage[qr0][c0],     sm.qstage[qr0][c0 + 1],     qhi[kb][0], qlo[kb][0]);
        split2(sm.qstage[qr0 + 8][c0], sm.qstage[qr0 + 8][c0 + 1], qhi[kb][1], qlo[kb][1]);
        split2(sm.qstage[qr0][c0 + 8],     sm.qstage[qr0][c0 + 9],     qhi[kb][2], qlo[kb][2]);
        split2(sm.qstage[qr0 + 8][c0 + 8], sm.qstage[qr0 + 8][c0 + 9], qhi[kb][3], qlo[kb][3]);
    }

    // packed-mask row pointers (mask independent of h)
    const unsigned* mr0 = g_mask_bits + ((size_t)b * S_ + q0 + qr0) * MW_ROW;
    const unsigned* mr1 = mr0 + 8 * MW_ROW;

    // =================== Sweep 1: row max + sum of exp ===================
    float m0 = -1e30f, m1 = -1e30f, l0 = 0.f, l1 = 0.f;
    for (int kc = 0; kc < NCH; kc++) {
        __syncthreads();
        load_kv(&sm, Kb, Vb, kc, tid, false);
        __syncthreads();

        unsigned pr00 = __ldg(mr0 + 2 * kc), pr01 = __ldg(mr0 + 2 * kc + 1);
        unsigned pr10 = __ldg(mr1 + 2 * kc), pr11 = __ldg(mr1 + 2 * kc + 1);

        float s[8][4];
        #pragma unroll
        for (int nb = 0; nb < 8; nb++)
            s[nb][0] = s[nb][1] = s[nb][2] = s[nb][3] = 0.f;
        #pragma unroll
        for (int kb = 0; kb < 4; kb++) {
            #pragma unroll
            for (int nb = 0; nb < 8; nb++) {
                const unsigned short* ph = &sm.kv.khi[nb * 8 + gid][kb * 16 + 2 * tig];
                const unsigned short* pl = &sm.kv.klo[nb * 8 + gid][kb * 16 + 2 * tig];
                unsigned bh0 = *(const unsigned*)ph;
                unsigned bh1 = *(const unsigned*)(ph + 8);
                unsigned bl0 = *(const unsigned*)pl;
                unsigned bl1 = *(const unsigned*)(pl + 8);
                mma16816(s[nb], qhi[kb], bh0, bh1);
                mma16816(s[nb], qlo[kb], bh0, bh1);
                mma16816(s[nb], qhi[kb], bl0, bl1);
            }
        }

        float rmax0 = -1e30f, rmax1 = -1e30f;
        #pragma unroll
        for (int nb = 0; nb < 8; nb++) {
            int sh = ((nb & 3) << 3) + 2 * tig;
            unsigned w0 = (nb < 4) ? pr00 : pr01;
            unsigned w1 = (nb < 4) ? pr10 : pr11;
            s[nb][0] = ((w0 >> sh) & 1)       ? -1e9f : s[nb][0] * SCALEF;
            s[nb][1] = ((w0 >> (sh + 1)) & 1) ? -1e9f : s[nb][1] * SCALEF;
            s[nb][2] = ((w1 >> sh) & 1)       ? -1e9f : s[nb][2] * SCALEF;
            s[nb][3] = ((w1 >> (sh + 1)) & 1) ? -1e9f : s[nb][3] * SCALEF;
            rmax0 = fmaxf(rmax0, fmaxf(s[nb][0], s[nb][1]));
            rmax1 = fmaxf(rmax1, fmaxf(s[nb][2], s[nb][3]));
        }
        rmax0 = fmaxf(rmax0, __shfl_xor_sync(0xffffffffu, rmax0, 1));
        rmax0 = fmaxf(rmax0, __shfl_xor_sync(0xffffffffu, rmax0, 2));
        rmax1 = fmaxf(rmax1, __shfl_xor_sync(0xffffffffu, rmax1, 1));
        rmax1 = fmaxf(rmax1, __shfl_xor_sync(0xffffffffu, rmax1, 2));

        float m0n = fmaxf(m0, rmax0), m1n = fmaxf(m1, rmax1);
        float e0 = 0.f, e1 = 0.f;
        #pragma unroll
        for (int nb = 0; nb < 8; nb++) {
            e0 += __expf(s[nb][0] - m0n) + __expf(s[nb][1] - m0n);
            e1 += __expf(s[nb][2] - m1n) + __expf(s[nb][3] - m1n);
        }
        e0 += __shfl_xor_sync(0xffffffffu, e0, 1);
        e0 += __shfl_xor_sync(0xffffffffu, e0, 2);
        e1 += __shfl_xor_sync(0xffffffffu, e1, 1);
        e1 += __shfl_xor_sync(0xffffffffu, e1, 2);
        l0 = l0 * __expf(m0 - m0n) + e0;  m0 = m0n;
        l1 = l1 * __expf(m1 - m1n) + e1;  m1 = m1n;
    }
    const float inv0 = 1.0f / l0;
    const float inv1 = 1.0f / l1;

    // =================== Sweep 2: P write + O += P @ V ===================
    float O[8][4];
    #pragma unroll
    for (int dn = 0; dn < 8; dn++)
        O[dn][0] = O[dn][1] = O[dn][2] = O[dn][3] = 0.f;

    float* arow0 = attn + (size_t)qr0 * S_;
    float* arow1 = attn + (size_t)(qr0 + 8) * S_;

    for (int kc = 0; kc < NCH; kc++) {
        __syncthreads();
        load_kv(&sm, Kb, Vb, kc, tid, true);
        __syncthreads();

        unsigned pr00 = __ldg(mr0 + 2 * kc), pr01 = __ldg(mr0 + 2 * kc + 1);
        unsigned pr10 = __ldg(mr1 + 2 * kc), pr11 = __ldg(mr1 + 2 * kc + 1);

        unsigned aphi[4][4], aplo[4][4];   // P as A-fragments for PV

        #pragma unroll
        for (int g = 0; g < 2; g++) {      // nb groups of 4 for ILP/regs
            float s[4][4];
            #pragma unroll
            for (int j = 0; j < 4; j++)
                s[j][0] = s[j][1] = s[j][2] = s[j][3] = 0.f;
            #pragma unroll
            for (int kb = 0; kb < 4; kb++) {
                #pragma unroll
                for (int j = 0; j < 4; j++) {
                    int nb = g * 4 + j;
                    const unsigned short* ph = &sm.kv.khi[nb * 8 + gid][kb * 16 + 2 * tig];
                    const unsigned short* pl = &sm.kv.klo[nb * 8 + gid][kb * 16 + 2 * tig];
                    unsigned bh0 = *(const unsigned*)ph;
                    unsigned bh1 = *(const unsigned*)(ph + 8);
                    unsigned bl0 = *(const unsigned*)pl;
                    unsigned bl1 = *(const unsigned*)(pl + 8);
                    mma16816(s[j], qhi[kb], bh0, bh1);
                    mma16816(s[j], qlo[kb], bh0, bh1);
                    mma16816(s[j], qhi[kb], bl0, bl1);
                }
            }
            #pragma unroll
            for (int j = 0; j < 4; j++) {
                int nb = g * 4 + j;
                int sh = ((nb & 3) << 3) + 2 * tig;
                unsigned w0 = (nb < 4) ? pr00 : pr01;
                unsigned w1 = (nb < 4) ? pr10 : pr11;
                float s0 = ((w0 >> sh) & 1)       ? -1e9f : s[j][0] * SCALEF;
                float s1 = ((w0 >> (sh + 1)) & 1) ? -1e9f : s[j][1] * SCALEF;
                float s2 = ((w1 >> sh) & 1)       ? -1e9f : s[j][2] * SCALEF;
                float s3 = ((w1 >> (sh + 1)) & 1) ? -1e9f : s[j][3] * SCALEF;
                float p0 = __expf(s0 - m0) * inv0;
                float p1 = __expf(s1 - m0) * inv0;
                float p2 = __expf(s2 - m1) * inv1;
                float p3 = __expf(s3 - m1) * inv1;
                int col = kc * KC + nb * 8 + 2 * tig;
                __stcs((float2*)(arow0 + col), make_float2(p0, p1));
                __stcs((float2*)(arow1 + col), make_float2(p2, p3));
                int kb2 = nb >> 1, jj = (nb & 1) << 1;
                split2(p0, p1, aphi[kb2][jj],     aplo[kb2][jj]);
                split2(p2, p3, aphi[kb2][jj + 1], aplo[kb2][jj + 1]);
            }
        }

        // O += P @ V   (V transposed in smem: vt[d][k])
        #pragma unroll
        for (int kb2 = 0; kb2 < 4; kb2++) {
            #pragma unroll
            for (int dn = 0; dn < 8; dn++) {
                const unsigned short* vh = &sm.kv.vthi[dn * 8 + gid][kb2 * 16 + 2 * tig];
                const unsigned short* vl = &sm.kv.vtlo[dn * 8 + gid][kb2 * 16 + 2 * tig];
                unsigned bh0 = *(const unsigned*)vh;
                unsigned bh1 = *(const unsigned*)(vh + 8);
                unsigned bl0 = *(const unsigned*)vl;
                unsigned bl1 = *(const unsigned*)(vl + 8);
                mma16816(O[dn], aphi[kb2], bh0, bh1);
                mma16816(O[dn], aplo[kb2], bh0, bh1);
                mma16816(O[dn], aphi[kb2], bl0, bl1);
            }
        }
    }

    // ---- store context ----
    #pragma unroll
    for (int dn = 0; dn < 8; dn++) {
        int c = dn * 8 + 2 * tig;
        *(float2*)(ctx + (size_t)qr0 * D_ + c)       = make_float2(O[dn][0], O[dn][1]);
        *(float2*)(ctx + (size_t)(qr0 + 8) * D_ + c) = make_float2(O[dn][2], O[dn][3]);
    }
}

// ---------------------------------------------------------------------------
extern "C" void kernel_launch(void* const* d_in, const int* in_sizes, int n_in,
                              void* d_out, int out_size) {
    const float* Q = (const float*)d_in[0];
    const float* K = (const float*)d_in[1];
    const float* V = (const float*)d_in[2];
    const unsigned char* M = (const unsigned char*)d_in[3];
    // d_in[4] = dim_key (constant 64, unused)

    detect_kernel<<<1, 256>>>((const unsigned*)M);
    pack_kernel<<<(MWORDS + 255) / 256, 256>>>(M);

    dim3 grid(S_ / QT, H_, B_);
    sdpa_kernel<<<grid, NTHR>>>(Q, K, V, (float*)d_out);
}

// round 4
// speedup vs baseline: 1.3151x; 1.3151x over previous
#include <cuda_runtime.h>
#include <cuda_bf16.h>
#include <cstdint>

#define B_    2
#define H_    16
#define S_    2048
#define D_    64
#define BH_   (B_*H_)
#define QT    128
#define KC    64
#define NCH   (S_/KC)
#define NTHR  256
#define SCALEF 0.125f
#define MWORDS (B_ * S_ * S_ / 32)
#define MW_ROW (S_ / 32)
#define RSTRIDE 20              // smem row stride in uint4 (320 B, bank-safe)

// ---------------------------------------------------------------------------
// Globals: fragment-ready K, V^T (bf16 hi/lo interleaved), packed mask
// ---------------------------------------------------------------------------
__device__ uint4 g_Kf[BH_][S_][16];       // 16 MB: [bh][k-row][kb*4+tig] 16B frags
__device__ uint4 g_Vf[BH_][D_][S_/4];     // 16 MB: [bh][d][sb*4+tig]
__device__ unsigned g_mask_bits[MWORDS];  // 1 MB

// ---------------------------------------------------------------------------
// Helpers
// ---------------------------------------------------------------------------
__device__ __forceinline__ void splitf(float x, unsigned short& hi, unsigned short& lo) {
    __nv_bfloat16 h = __float2bfloat16_rn(x);
    hi = __bfloat16_as_ushort(h);
    lo = __bfloat16_as_ushort(__float2bfloat16_rn(x - __bfloat162float(h)));
}
__device__ __forceinline__ void split2(float a, float b, unsigned& hi, unsigned& lo) {
    unsigned short ah, al, bh, bl;
    splitf(a, ah, al);
    splitf(b, bh, bl);
    hi = (unsigned)ah | ((unsigned)bh << 16);
    lo = (unsigned)al | ((unsigned)bl << 16);
}
__device__ __forceinline__ void mma16816(float* c, const unsigned* a, unsigned b0, unsigned b1) {
    asm volatile(
        "mma.sync.aligned.m16n8k16.row.col.f32.bf16.bf16.f32 "
        "{%0,%1,%2,%3}, {%4,%5,%6,%7}, {%8,%9}, {%0,%1,%2,%3};"
        : "+f"(c[0]), "+f"(c[1]), "+f"(c[2]), "+f"(c[3])
        : "r"(a[0]), "r"(a[1]), "r"(a[2]), "r"(a[3]), "r"(b0), "r"(b1));
}
__device__ __forceinline__ void cpa16(void* smem, const void* g) {
    unsigned s = (unsigned)__cvta_generic_to_shared(smem);
    asm volatile("cp.async.cg.shared.global [%0], [%1], 16;" :: "r"(s), "l"(g));
}
#define CPA_COMMIT() asm volatile("cp.async.commit_group;")
template<int N> __device__ __forceinline__ void cpa_wait() {
    asm volatile("cp.async.wait_group %0;" :: "n"(N));
}

// ---------------------------------------------------------------------------
// Mask pack (detect dtype inline: u8-bool vs 4-byte int/float)
// ---------------------------------------------------------------------------
__device__ __forceinline__ unsigned pk4nz(unsigned v) {
    unsigned b = __vminu4(v, 0x01010101u);
    return (b | (b >> 7) | (b >> 14) | (b >> 21)) & 0xFu;
}
__global__ void pack_kernel(const unsigned char* __restrict__ m8) {
    const unsigned* mw = (const unsigned*)m8;
    int other = 0;
    for (int i = threadIdx.x; i < 2048; i += 256) {
        unsigned x = mw[i];
        if (x != 0u && x != 1u && x != 0x3F800000u) other = 1;
    }
    int is_u8 = __syncthreads_or(other);
    int w = blockIdx.x * blockDim.x + threadIdx.x;
    if (w >= MWORDS) return;
    unsigned bits = 0;
    if (is_u8) {
        const uint4* p = (const uint4*)(m8 + (size_t)w * 32);
        uint4 u0 = p[0], u1 = p[1];
        bits = pk4nz(u0.x) | (pk4nz(u0.y) << 4) | (pk4nz(u0.z) << 8) | (pk4nz(u0.w) << 12)
             | (pk4nz(u1.x) << 16) | (pk4nz(u1.y) << 20) | (pk4nz(u1.z) << 24) | (pk4nz(u1.w) << 28);
    } else {
        const uint4* p = (const uint4*)m8 + (size_t)w * 8;
        #pragma unroll
        for (int j = 0; j < 8; j++) {
            uint4 u = p[j];
            bits |= ((unsigned)(u.x != 0u) << (4 * j))
                  | ((unsigned)(u.y != 0u) << (4 * j + 1))
                  | ((unsigned)(u.z != 0u) << (4 * j + 2))
                  | ((unsigned)(u.w != 0u) << (4 * j + 3));
        }
    }
    g_mask_bits[w] = bits;
}

// ---------------------------------------------------------------------------
// Prep: build fragment-ready bf16 hi/lo K and V^T in gmem (one kernel,
// K path = blocks [0,4096), V path = blocks [4096,5120))
// ---------------------------------------------------------------------------
__global__ void prep_kernel(const float* __restrict__ K, const float* __restrict__ V) {
    __shared__ float vt[64][65];
    if (blockIdx.x < 4096) {
        int t   = blockIdx.x * 256 + threadIdx.x;     // one uint4 out per thread
        int bh  = t >> 15;
        int rem = t & 32767;
        int r   = rem >> 4;
        int u   = rem & 15;
        int kb  = u >> 2, tig = u & 3;
        int d0  = kb * 16 + 2 * tig;
        const float* row = K + ((size_t)bh * S_ + r) * D_;
        unsigned h01, l01, h89, l89;
        split2(row[d0],     row[d0 + 1], h01, l01);
        split2(row[d0 + 8], row[d0 + 9], h89, l89);
        g_Kf[bh][r][u] = make_uint4(h01, l01, h89, l89);
    } else {
        int blk = blockIdx.x - 4096;
        int bh  = blk >> 5;
        int sc  = blk & 31;                           // 64-row s-tile
        const float* Vb = V + ((size_t)bh * S_ + sc * 64) * D_;
        for (int i = threadIdx.x; i < 64 * 64; i += 256) {
            int s = i >> 6, d = i & 63;
            vt[s][d] = Vb[s * D_ + d];
        }
        __syncthreads();
        for (int o = threadIdx.x; o < 1024; o += 256) {
            int d = o >> 4, u = o & 15;
            int sbl = u >> 2, tig = u & 3;
            int s0 = sbl * 16 + 2 * tig;
            unsigned h01, l01, h89, l89;
            split2(vt[s0][d],     vt[s0 + 1][d], h01, l01);
            split2(vt[s0 + 8][d], vt[s0 + 9][d], h89, l89);
            g_Vf[bh][d][(sc * 4 + sbl) * 4 + tig] = make_uint4(h01, l01, h89, l89);
        }
    }
}

// ---------------------------------------------------------------------------
// Chunk prefetch (cp.async, 16B granules)
// ---------------------------------------------------------------------------
__device__ __forceinline__ void pf_k(uint4* kb, int bh, int kc, int tid) {
    const uint4* src = &g_Kf[bh][kc * KC][0];
    #pragma unroll
    for (int i = 0; i < 4; i++) {
        int t = tid + i * NTHR;
        int r = t >> 4, u = t & 15;
        cpa16(kb + r * RSTRIDE + u, src + t);
    }
}
__device__ __forceinline__ void pf_v(uint4* vb, int bh, int kc, int tid) {
    #pragma unroll
    for (int i = 0; i < 4; i++) {
        int t = tid + i * NTHR;
        int d = t >> 4, u = t & 15;
        cpa16(vb + d * RSTRIDE + u, &g_Vf[bh][d][kc * 16 + u]);
    }
}

// ---------------------------------------------------------------------------
// Main kernel. CTA = 128 q rows of one (b,h); 8 warps × 16 rows.
// Sweep 1: 1-MMA scores -> m, l (denominator-only precision, ~1e-4).
// Sweep 2: 3-MMA split scores -> write p = exp(s-m)/l; O += P@V (3-MMA).
// ---------------------------------------------------------------------------
__global__ void __launch_bounds__(NTHR, 1)
sdpa_kernel(const float* __restrict__ Q, float* __restrict__ out) {
    extern __shared__ uint4 dsm[];
    uint4* Kb0 = dsm;
    uint4* Kb1 = dsm + 1280;
    uint4* Vb0 = dsm + 2560;
    uint4* Vb1 = dsm + 3840;

    const int tid  = threadIdx.x;
    const int w    = tid >> 5;
    const int lane = tid & 31;
    const int gid  = lane >> 2;
    const int tig  = lane & 3;
    const int b    = blockIdx.z, h = blockIdx.y;
    const int q0   = blockIdx.x * QT;
    const int bh   = b * H_ + h;

    const float* Qb = Q + ((size_t)bh * S_ + q0) * D_;
    float* ctx  = out + ((size_t)bh * S_ + q0) * D_;
    float* attn = out + (size_t)B_ * H_ * S_ * D_ + ((size_t)bh * S_ + q0) * S_;

    const int qr0 = w * 16 + gid;

    // ---- Q fragments straight from gmem (one-time) ----
    unsigned qhi[4][4], qlo[4][4];
    #pragma unroll
    for (int kb = 0; kb < 4; kb++) {
        int c0 = kb * 16 + 2 * tig;
        float2 a = *(const float2*)(Qb + (size_t)qr0 * D_ + c0);
        float2 b2 = *(const float2*)(Qb + (size_t)(qr0 + 8) * D_ + c0);
        float2 c = *(const float2*)(Qb + (size_t)qr0 * D_ + c0 + 8);
        float2 d = *(const float2*)(Qb + (size_t)(qr0 + 8) * D_ + c0 + 8);
        split2(a.x, a.y, qhi[kb][0], qlo[kb][0]);
        split2(b2.x, b2.y, qhi[kb][1], qlo[kb][1]);
        split2(c.x, c.y, qhi[kb][2], qlo[kb][2]);
        split2(d.x, d.y, qhi[kb][3], qlo[kb][3]);
    }

    const unsigned* mr0 = g_mask_bits + ((size_t)b * S_ + q0 + qr0) * MW_ROW;
    const unsigned* mr1 = mr0 + 8 * MW_ROW;

    // =================== Sweep 1: m, l (K only, 1 MMA/tile) ===================
    float m0 = -1e30f, m1 = -1e30f, l0 = 0.f, l1 = 0.f;

    pf_k(Kb0, bh, 0, tid); CPA_COMMIT();
    pf_k(Kb1, bh, 1, tid); CPA_COMMIT();

    for (int kc = 0; kc < NCH; kc++) {
        if (kc + 1 < NCH) cpa_wait<1>(); else cpa_wait<0>();
        __syncthreads();
        const uint4* Kc = (kc & 1) ? Kb1 : Kb0;

        unsigned pr00 = __ldg(mr0 + 2 * kc), pr01 = __ldg(mr0 + 2 * kc + 1);
        unsigned pr10 = __ldg(mr1 + 2 * kc), pr11 = __ldg(mr1 + 2 * kc + 1);

        float s[8][4];
        #pragma unroll
        for (int nb = 0; nb < 8; nb++)
            s[nb][0] = s[nb][1] = s[nb][2] = s[nb][3] = 0.f;
        #pragma unroll
        for (int kb = 0; kb < 4; kb++) {
            #pragma unroll
            for (int nb = 0; nb < 8; nb++) {
                uint4 f = Kc[(nb * 8 + gid) * RSTRIDE + kb * 4 + tig];
                mma16816(s[nb], qhi[kb], f.x, f.z);
            }
        }
        __syncthreads();
        if (kc + 2 < NCH) { pf_k((kc & 1) ? Kb1 : Kb0, bh, kc + 2, tid); CPA_COMMIT(); }

        float rmax0 = -1e30f, rmax1 = -1e30f;
        #pragma unroll
        for (int nb = 0; nb < 8; nb++) {
            int sh = ((nb & 3) << 3) + 2 * tig;
            unsigned w0 = (nb < 4) ? pr00 : pr01;
            unsigned w1 = (nb < 4) ? pr10 : pr11;
            s[nb][0] = ((w0 >> sh) & 1)       ? -1e9f : s[nb][0] * SCALEF;
            s[nb][1] = ((w0 >> (sh + 1)) & 1) ? -1e9f : s[nb][1] * SCALEF;
            s[nb][2] = ((w1 >> sh) & 1)       ? -1e9f : s[nb][2] * SCALEF;
            s[nb][3] = ((w1 >> (sh + 1)) & 1) ? -1e9f : s[nb][3] * SCALEF;
            rmax0 = fmaxf(rmax0, fmaxf(s[nb][0], s[nb][1]));
            rmax1 = fmaxf(rmax1, fmaxf(s[nb][2], s[nb][3]));
        }
        rmax0 = fmaxf(rmax0, __shfl_xor_sync(0xffffffffu, rmax0, 1));
        rmax0 = fmaxf(rmax0, __shfl_xor_sync(0xffffffffu, rmax0, 2));
        rmax1 = fmaxf(rmax1, __shfl_xor_sync(0xffffffffu, rmax1, 1));
        rmax1 = fmaxf(rmax1, __shfl_xor_sync(0xffffffffu, rmax1, 2));

        float m0n = fmaxf(m0, rmax0), m1n = fmaxf(m1, rmax1);
        float e0 = 0.f, e1 = 0.f;
        #pragma unroll
        for (int nb = 0; nb < 8; nb++) {
            e0 += __expf(s[nb][0] - m0n) + __expf(s[nb][1] - m0n);
            e1 += __expf(s[nb][2] - m1n) + __expf(s[nb][3] - m1n);
        }
        e0 += __shfl_xor_sync(0xffffffffu, e0, 1);
        e0 += __shfl_xor_sync(0xffffffffu, e0, 2);
        e1 += __shfl_xor_sync(0xffffffffu, e1, 1);
        e1 += __shfl_xor_sync(0xffffffffu, e1, 2);
        l0 = l0 * __expf(m0 - m0n) + e0;  m0 = m0n;
        l1 = l1 * __expf(m1 - m1n) + e1;  m1 = m1n;
    }
    const float inv0 = 1.0f / l0;
    const float inv1 = 1.0f / l1;
    __syncthreads();

    // =================== Sweep 2: P writes + O += P @ V ===================
    float O[8][4];
    #pragma unroll
    for (int dn = 0; dn < 8; dn++)
        O[dn][0] = O[dn][1] = O[dn][2] = O[dn][3] = 0.f;

    float* arow0 = attn + (size_t)qr0 * S_;
    float* arow1 = attn + (size_t)(qr0 + 8) * S_;

    pf_k(Kb0, bh, 0, tid); pf_v(Vb0, bh, 0, tid); CPA_COMMIT();
    pf_k(Kb1, bh, 1, tid); pf_v(Vb1, bh, 1, tid); CPA_COMMIT();

    for (int kc = 0; kc < NCH; kc++) {
        if (kc + 1 < NCH) cpa_wait<1>(); else cpa_wait<0>();
        __syncthreads();
        const uint4* Kc = (kc & 1) ? Kb1 : Kb0;
        const uint4* Vc = (kc & 1) ? Vb1 : Vb0;

        unsigned pr00 = __ldg(mr0 + 2 * kc), pr01 = __ldg(mr0 + 2 * kc + 1);
        unsigned pr10 = __ldg(mr1 + 2 * kc), pr11 = __ldg(mr1 + 2 * kc + 1);

        unsigned aphi[4][4], aplo[4][4];

        #pragma unroll
        for (int g = 0; g < 2; g++) {
            float s[4][4];
            #pragma unroll
            for (int j = 0; j < 4; j++)
                s[j][0] = s[j][1] = s[j][2] = s[j][3] = 0.f;
            #pragma unroll
            for (int kb = 0; kb < 4; kb++) {
                #pragma unroll
                for (int j = 0; j < 4; j++) {
                    int nb = g * 4 + j;
                    uint4 f = Kc[(nb * 8 + gid) * RSTRIDE + kb * 4 + tig];
                    mma16816(s[j], qhi[kb], f.x, f.z);
                    mma16816(s[j], qlo[kb], f.x, f.z);
                    mma16816(s[j], qhi[kb], f.y, f.w);
                }
            }
            #pragma unroll
            for (int j = 0; j < 4; j++) {
                int nb = g * 4 + j;
                int sh = ((nb & 3) << 3) + 2 * tig;
                unsigned w0 = (nb < 4) ? pr00 : pr01;
                unsigned w1 = (nb < 4) ? pr10 : pr11;
                float s0 = ((w0 >> sh) & 1)       ? -1e9f : s[j][0] * SCALEF;
                float s1 = ((w0 >> (sh + 1)) & 1) ? -1e9f : s[j][1] * SCALEF;
                float s2 = ((w1 >> sh) & 1)       ? -1e9f : s[j][2] * SCALEF;
                float s3 = ((w1 >> (sh + 1)) & 1) ? -1e9f : s[j][3] * SCALEF;
                float p0 = __expf(s0 - m0) * inv0;
                float p1 = __expf(s1 - m0) * inv0;
                float p2 = __expf(s2 - m1) * inv1;
                float p3 = __expf(s3 - m1) * inv1;
                int col = kc * KC + nb * 8 + 2 * tig;
                __stcs((float2*)(arow0 + col), make_float2(p0, p1));
                __stcs((float2*)(arow1 + col), make_float2(p2, p3));
                int kb2 = nb >> 1, jj = (nb & 1) << 1;
                split2(p0, p1, aphi[kb2][jj],     aplo[kb2][jj]);
                split2(p2, p3, aphi[kb2][jj + 1], aplo[kb2][jj + 1]);
            }
        }

        // O += P @ V
        #pragma unroll
        for (int kb2 = 0; kb2 < 4; kb2++) {
            #pragma unroll
            for (int dn = 0; dn < 8; dn++) {
                uint4 f = Vc[(dn * 8 + gid) * RSTRIDE + kb2 * 4 + tig];
                mma16816(O[dn], aphi[kb2], f.x, f.z);
                mma16816(O[dn], aplo[kb2], f.x, f.z);
                mma16816(O[dn], aphi[kb2], f.y, f.w);
            }
        }
        __syncthreads();
        if (kc + 2 < NCH) {
            uint4* kn = (kc & 1) ? Kb1 : Kb0;
            uint4* vn = (kc & 1) ? Vb1 : Vb0;
            pf_k(kn, bh, kc + 2, tid); pf_v(vn, bh, kc + 2, tid); CPA_COMMIT();
        }
    }

    // ---- store context ----
    #pragma unroll
    for (int dn = 0; dn < 8; dn++) {
        int c = dn * 8 + 2 * tig;
        *(float2*)(ctx + (size_t)qr0 * D_ + c)       = make_float2(O[dn][0], O[dn][1]);
        *(float2*)(ctx + (size_t)(qr0 + 8) * D_ + c) = make_float2(O[dn][2], O[dn][3]);
    }
}

// ---------------------------------------------------------------------------
extern "C" void kernel_launch(void* const* d_in, const int* in_sizes, int n_in,
                              void* d_out, int out_size) {
    const float* Q = (const float*)d_in[0];
    const float* K = (const float*)d_in[1];
    const float* V = (const float*)d_in[2];
    const unsigned char* M = (const unsigned char*)d_in[3];

    cudaFuncSetAttribute(sdpa_kernel, cudaFuncAttributeMaxDynamicSharedMemorySize, 81920);

    pack_kernel<<<(MWORDS + 255) / 256, 256>>>(M);
    prep_kernel<<<5120, 256>>>(K, V);

    dim3 grid(S_ / QT, H_, B_);
    sdpa_kernel<<<grid, NTHR, 81920>>>(Q, (float*)d_out);
}

// round 5
// speedup vs baseline: 1.3153x; 1.0001x over previous
#include <cuda_runtime.h>
#include <cuda_bf16.h>
#include <cstdint>

#define B_    2
#define H_    16
#define S_    2048
#define D_    64
#define BH_   (B_*H_)
#define QT    128
#define KC    64
#define NCH   (S_/KC)
#define NTHR  256
#define SCALEF 0.125f
#define MWORDS (B_ * S_ * S_ / 32)
#define MW_ROW (S_ / 32)
#define RSTRIDE 20              // smem row stride in uint4 (320 B, bank-safe)

// ---------------------------------------------------------------------------
// Globals: fragment-ready K, V^T (bf16 hi/lo interleaved), packed mask
// ---------------------------------------------------------------------------
__device__ uint4 g_Kf[BH_][S_][16];       // 16 MB: [bh][k-row][kb*4+tig] 16B frags
__device__ uint4 g_Vf[BH_][D_][S_/4];     // 16 MB: [bh][d][sb*4+tig]
__device__ unsigned g_mask_bits[MWORDS];  // 1 MB

// ---------------------------------------------------------------------------
// Helpers
// ---------------------------------------------------------------------------
__device__ __forceinline__ void splitf(float x, unsigned short& hi, unsigned short& lo) {
    __nv_bfloat16 h = __float2bfloat16_rn(x);
    hi = __bfloat16_as_ushort(h);
    lo = __bfloat16_as_ushort(__float2bfloat16_rn(x - __bfloat162float(h)));
}
__device__ __forceinline__ void split2(float a, float b, unsigned& hi, unsigned& lo) {
    unsigned short ah, al, bh, bl;
    splitf(a, ah, al);
    splitf(b, bh, bl);
    hi = (unsigned)ah | ((unsigned)bh << 16);
    lo = (unsigned)al | ((unsigned)bl << 16);
}
__device__ __forceinline__ void mma16816(float* c, const unsigned* a, unsigned b0, unsigned b1) {
    asm volatile(
        "mma.sync.aligned.m16n8k16.row.col.f32.bf16.bf16.f32 "
        "{%0,%1,%2,%3}, {%4,%5,%6,%7}, {%8,%9}, {%0,%1,%2,%3};"
        : "+f"(c[0]), "+f"(c[1]), "+f"(c[2]), "+f"(c[3])
        : "r"(a[0]), "r"(a[1]), "r"(a[2]), "r"(a[3]), "r"(b0), "r"(b1));
}
__device__ __forceinline__ void cpa16(void* smem, const void* g) {
    unsigned s = (unsigned)__cvta_generic_to_shared(smem);
    asm volatile("cp.async.cg.shared.global [%0], [%1], 16;" :: "r"(s), "l"(g));
}
#define CPA_COMMIT() asm volatile("cp.async.commit_group;")
template<int N> __device__ __forceinline__ void cpa_wait() {
    asm volatile("cp.async.wait_group %0;" :: "n"(N));
}

// ---------------------------------------------------------------------------
// Mask pack (detect dtype inline: u8-bool vs 4-byte int/float)
// ---------------------------------------------------------------------------
__device__ __forceinline__ unsigned pk4nz(unsigned v) {
    unsigned b = __vminu4(v, 0x01010101u);
    return (b | (b >> 7) | (b >> 14) | (b >> 21)) & 0xFu;
}
__global__ void pack_kernel(const unsigned char* __restrict__ m8) {
    const unsigned* mw = (const unsigned*)m8;
    int other = 0;
    for (int i = threadIdx.x; i < 2048; i += 256) {
        unsigned x = mw[i];
        if (x != 0u && x != 1u && x != 0x3F800000u) other = 1;
    }
    int is_u8 = __syncthreads_or(other);
    int w = blockIdx.x * blockDim.x + threadIdx.x;
    if (w >= MWORDS) return;
    unsigned bits = 0;
    if (is_u8) {
        const uint4* p = (const uint4*)(m8 + (size_t)w * 32);
        uint4 u0 = p[0], u1 = p[1];
        bits = pk4nz(u0.x) | (pk4nz(u0.y) << 4) | (pk4nz(u0.z) << 8) | (pk4nz(u0.w) << 12)
             | (pk4nz(u1.x) << 16) | (pk4nz(u1.y) << 20) | (pk4nz(u1.z) << 24) | (pk4nz(u1.w) << 28);
    } else {
        const uint4* p = (const uint4*)m8 + (size_t)w * 8;
        #pragma unroll
        for (int j = 0; j < 8; j++) {
            uint4 u = p[j];
            bits |= ((unsigned)(u.x != 0u) << (4 * j))
                  | ((unsigned)(u.y != 0u) << (4 * j + 1))
                  | ((unsigned)(u.z != 0u) << (4 * j + 2))
                  | ((unsigned)(u.w != 0u) << (4 * j + 3));
        }
    }
    g_mask_bits[w] = bits;
}

// ---------------------------------------------------------------------------
// Prep: build fragment-ready bf16 hi/lo K and V^T in gmem (one kernel,
// K path = blocks [0,4096), V path = blocks [4096,5120))
// ---------------------------------------------------------------------------
__global__ void prep_kernel(const float* __restrict__ K, const float* __restrict__ V) {
    __shared__ float vt[64][65];
    if (blockIdx.x < 4096) {
        int t   = blockIdx.x * 256 + threadIdx.x;     // one uint4 out per thread
        int bh  = t >> 15;
        int rem = t & 32767;
        int r   = rem >> 4;
        int u   = rem & 15;
        int kb  = u >> 2, tig = u & 3;
        int d0  = kb * 16 + 2 * tig;
        const float* row = K + ((size_t)bh * S_ + r) * D_;
        unsigned h01, l01, h89, l89;
        split2(row[d0],     row[d0 + 1], h01, l01);
        split2(row[d0 + 8], row[d0 + 9], h89, l89);
        g_Kf[bh][r][u] = make_uint4(h01, l01, h89, l89);
    } else {
        int blk = blockIdx.x - 4096;
        int bh  = blk >> 5;
        int sc  = blk & 31;                           // 64-row s-tile
        const float* Vb = V + ((size_t)bh * S_ + sc * 64) * D_;
        for (int i = threadIdx.x; i < 64 * 64; i += 256) {
            int s = i >> 6, d = i & 63;
            vt[s][d] = Vb[s * D_ + d];
        }
        __syncthreads();
        for (int o = threadIdx.x; o < 1024; o += 256) {
            int d = o >> 4, u = o & 15;
            int sbl = u >> 2, tig = u & 3;
            int s0 = sbl * 16 + 2 * tig;
            unsigned h01, l01, h89, l89;
            split2(vt[s0][d],     vt[s0 + 1][d], h01, l01);
            split2(vt[s0 + 8][d], vt[s0 + 9][d], h89, l89);
            g_Vf[bh][d][(sc * 4 + sbl) * 4 + tig] = make_uint4(h01, l01, h89, l89);
        }
    }
}

// ---------------------------------------------------------------------------
// Chunk prefetch (cp.async, 16B granules)
// ---------------------------------------------------------------------------
__device__ __forceinline__ void pf_k(uint4* kb, int bh, int kc, int tid) {
    const uint4* src = &g_Kf[bh][kc * KC][0];
    #pragma unroll
    for (int i = 0; i < 4; i++) {
        int t = tid + i * NTHR;
        int r = t >> 4, u = t & 15;
        cpa16(kb + r * RSTRIDE + u, src + t);
    }
}
__device__ __forceinline__ void pf_v(uint4* vb, int bh, int kc, int tid) {
    #pragma unroll
    for (int i = 0; i < 4; i++) {
        int t = tid + i * NTHR;
        int d = t >> 4, u = t & 15;
        cpa16(vb + d * RSTRIDE + u, &g_Vf[bh][d][kc * 16 + u]);
    }
}

// ---------------------------------------------------------------------------
// Main kernel. CTA = 128 q rows of one (b,h); 8 warps × 16 rows.
// Sweep 1: 1-MMA scores -> m, l (denominator-only precision, ~1e-4).
// Sweep 2: 3-MMA split scores -> write p = exp(s-m)/l; O += P@V (3-MMA).
// ---------------------------------------------------------------------------
__global__ void __launch_bounds__(NTHR, 1)
sdpa_kernel(const float* __restrict__ Q, float* __restrict__ out) {
    extern __shared__ uint4 dsm[];
    uint4* Kb0 = dsm;
    uint4* Kb1 = dsm + 1280;
    uint4* Vb0 = dsm + 2560;
    uint4* Vb1 = dsm + 3840;

    const int tid  = threadIdx.x;
    const int w    = tid >> 5;
    const int lane = tid & 31;
    const int gid  = lane >> 2;
    const int tig  = lane & 3;
    const int b    = blockIdx.z, h = blockIdx.y;
    const int q0   = blockIdx.x * QT;
    const int bh   = b * H_ + h;

    const float* Qb = Q + ((size_t)bh * S_ + q0) * D_;
    float* ctx  = out + ((size_t)bh * S_ + q0) * D_;
    float* attn = out + (size_t)B_ * H_ * S_ * D_ + ((size_t)bh * S_ + q0) * S_;

    const int qr0 = w * 16 + gid;

    // ---- Q fragments straight from gmem (one-time) ----
    unsigned qhi[4][4], qlo[4][4];
    #pragma unroll
    for (int kb = 0; kb < 4; kb++) {
        int c0 = kb * 16 + 2 * tig;
        float2 a = *(const float2*)(Qb + (size_t)qr0 * D_ + c0);
        float2 b2 = *(const float2*)(Qb + (size_t)(qr0 + 8) * D_ + c0);
        float2 c = *(const float2*)(Qb + (size_t)qr0 * D_ + c0 + 8);
        float2 d = *(const float2*)(Qb + (size_t)(qr0 + 8) * D_ + c0 + 8);
        split2(a.x, a.y, qhi[kb][0], qlo[kb][0]);
        split2(b2.x, b2.y, qhi[kb][1], qlo[kb][1]);
        split2(c.x, c.y, qhi[kb][2], qlo[kb][2]);
        split2(d.x, d.y, qhi[kb][3], qlo[kb][3]);
    }

    const unsigned* mr0 = g_mask_bits + ((size_t)b * S_ + q0 + qr0) * MW_ROW;
    const unsigned* mr1 = mr0 + 8 * MW_ROW;

    // =================== Sweep 1: m, l (K only, 1 MMA/tile) ===================
    float m0 = -1e30f, m1 = -1e30f, l0 = 0.f, l1 = 0.f;

    pf_k(Kb0, bh, 0, tid); CPA_COMMIT();
    pf_k(Kb1, bh, 1, tid); CPA_COMMIT();

    for (int kc = 0; kc < NCH; kc++) {
        if (kc + 1 < NCH) cpa_wait<1>(); else cpa_wait<0>();
        __syncthreads();
        const uint4* Kc = (kc & 1) ? Kb1 : Kb0;

        unsigned pr00 = __ldg(mr0 + 2 * kc), pr01 = __ldg(mr0 + 2 * kc + 1);
        unsigned pr10 = __ldg(mr1 + 2 * kc), pr11 = __ldg(mr1 + 2 * kc + 1);

        float s[8][4];
        #pragma unroll
        for (int nb = 0; nb < 8; nb++)
            s[nb][0] = s[nb][1] = s[nb][2] = s[nb][3] = 0.f;
        #pragma unroll
        for (int kb = 0; kb < 4; kb++) {
            #pragma unroll
            for (int nb = 0; nb < 8; nb++) {
                uint4 f = Kc[(nb * 8 + gid) * RSTRIDE + kb * 4 + tig];
                mma16816(s[nb], qhi[kb], f.x, f.z);
            }
        }
        __syncthreads();
        if (kc + 2 < NCH) { pf_k((kc & 1) ? Kb1 : Kb0, bh, kc + 2, tid); CPA_COMMIT(); }

        float rmax0 = -1e30f, rmax1 = -1e30f;
        #pragma unroll
        for (int nb = 0; nb < 8; nb++) {
            int sh = ((nb & 3) << 3) + 2 * tig;
            unsigned w0 = (nb < 4) ? pr00 : pr01;
            unsigned w1 = (nb < 4) ? pr10 : pr11;
            s[nb][0] = ((w0 >> sh) & 1)       ? -1e9f : s[nb][0] * SCALEF;
            s[nb][1] = ((w0 >> (sh + 1)) & 1) ? -1e9f : s[nb][1] * SCALEF;
            s[nb][2] = ((w1 >> sh) & 1)       ? -1e9f : s[nb][2] * SCALEF;
            s[nb][3] = ((w1 >> (sh + 1)) & 1) ? -1e9f : s[nb][3] * SCALEF;
            rmax0 = fmaxf(rmax0, fmaxf(s[nb][0], s[nb][1]));
            rmax1 = fmaxf(rmax1, fmaxf(s[nb][2], s[nb][3]));
        }
        rmax0 = fmaxf(rmax0, __shfl_xor_sync(0xffffffffu, rmax0, 1));
        rmax0 = fmaxf(rmax0, __shfl_xor_sync(0xffffffffu, rmax0, 2));
        rmax1 = fmaxf(rmax1, __shfl_xor_sync(0xffffffffu, rmax1, 1));
        rmax1 = fmaxf(rmax1, __shfl_xor_sync(0xffffffffu, rmax1, 2));

        float m0n = fmaxf(m0, rmax0), m1n = fmaxf(m1, rmax1);
        float e0 = 0.f, e1 = 0.f;
        #pragma unroll
        for (int nb = 0; nb < 8; nb++) {
            e0 += __expf(s[nb][0] - m0n) + __expf(s[nb][1] - m0n);
            e1 += __expf(s[nb][2] - m1n) + __expf(s[nb][3] - m1n);
        }
        e0 += __shfl_xor_sync(0xffffffffu, e0, 1);
        e0 += __shfl_xor_sync(0xffffffffu, e0, 2);
        e1 += __shfl_xor_sync(0xffffffffu, e1, 1);
        e1 += __shfl_xor_sync(0xffffffffu, e1, 2);
        l0 = l0 * __expf(m0 - m0n) + e0;  m0 = m0n;
        l1 = l1 * __expf(m1 - m1n) + e1;  m1 = m1n;
    }
    const float inv0 = 1.0f / l0;
    const float inv1 = 1.0f / l1;
    __syncthreads();

    // =================== Sweep 2: P writes + O += P @ V ===================
    float O[8][4];
    #pragma unroll
    for (int dn = 0; dn < 8; dn++)
        O[dn][0] = O[dn][1] = O[dn][2] = O[dn][3] = 0.f;

    float* arow0 = attn + (size_t)qr0 * S_;
    float* arow1 = attn + (size_t)(qr0 + 8) * S_;

    pf_k(Kb0, bh, 0, tid); pf_v(Vb0, bh, 0, tid); CPA_COMMIT();
    pf_k(Kb1, bh, 1, tid); pf_v(Vb1, bh, 1, tid); CPA_COMMIT();

    for (int kc = 0; kc < NCH; kc++) {
        if (kc + 1 < NCH) cpa_wait<1>(); else cpa_wait<0>();
        __syncthreads();
        const uint4* Kc = (kc & 1) ? Kb1 : Kb0;
        const uint4* Vc = (kc & 1) ? Vb1 : Vb0;

        unsigned pr00 = __ldg(mr0 + 2 * kc), pr01 = __ldg(mr0 + 2 * kc + 1);
        unsigned pr10 = __ldg(mr1 + 2 * kc), pr11 = __ldg(mr1 + 2 * kc + 1);

        unsigned aphi[4][4], aplo[4][4];

        #pragma unroll
        for (int g = 0; g < 2; g++) {
            float s[4][4];
            #pragma unroll
            for (int j = 0; j < 4; j++)
                s[j][0] = s[j][1] = s[j][2] = s[j][3] = 0.f;
            #pragma unroll
            for (int kb = 0; kb < 4; kb++) {
                #pragma unroll
                for (int j = 0; j < 4; j++) {
                    int nb = g * 4 + j;
                    uint4 f = Kc[(nb * 8 + gid) * RSTRIDE + kb * 4 + tig];
                    mma16816(s[j], qhi[kb], f.x, f.z);
                    mma16816(s[j], qlo[kb], f.x, f.z);
                    mma16816(s[j], qhi[kb], f.y, f.w);
                }
            }
            #pragma unroll
            for (int j = 0; j < 4; j++) {
                int nb = g * 4 + j;
                int sh = ((nb & 3) << 3) + 2 * tig;
                unsigned w0 = (nb < 4) ? pr00 : pr01;
                unsigned w1 = (nb < 4) ? pr10 : pr11;
                float s0 = ((w0 >> sh) & 1)       ? -1e9f : s[j][0] * SCALEF;
                float s1 = ((w0 >> (sh + 1)) & 1) ? -1e9f : s[j][1] * SCALEF;
                float s2 = ((w1 >> sh) & 1)       ? -1e9f : s[j][2] * SCALEF;
                float s3 = ((w1 >> (sh + 1)) & 1) ? -1e9f : s[j][3] * SCALEF;
                float p0 = __expf(s0 - m0) * inv0;
                float p1 = __expf(s1 - m0) * inv0;
                float p2 = __expf(s2 - m1) * inv1;
                float p3 = __expf(s3 - m1) * inv1;
                int col = kc * KC + nb * 8 + 2 * tig;
                __stcs((float2*)(arow0 + col), make_float2(p0, p1));
                __stcs((float2*)(arow1 + col), make_float2(p2, p3));
                int kb2 = nb >> 1, jj = (nb & 1) << 1;
                split2(p0, p1, aphi[kb2][jj],     aplo[kb2][jj]);
                split2(p2, p3, aphi[kb2][jj + 1], aplo[kb2][jj + 1]);
            }
        }

        // O += P @ V
        #pragma unroll
        for (int kb2 = 0; kb2 < 4; kb2++) {
            #pragma unroll
            for (int dn = 0; dn < 8; dn++) {
                uint4 f = Vc[(dn * 8 + gid) * RSTRIDE + kb2 * 4 + tig];
                mma16816(O[dn], aphi[kb2], f.x, f.z);
                mma16816(O[dn], aplo[kb2], f.x, f.z);
                mma16816(O[dn], aphi[kb2], f.y, f.w);
            }
        }
        __syncthreads();
        if (kc + 2 < NCH) {
            uint4* kn = (kc & 1) ? Kb1 : Kb0;
            uint4* vn = (kc & 1) ? Vb1 : Vb0;
            pf_k(kn, bh, kc + 2, tid); pf_v(vn, bh, kc + 2, tid); CPA_COMMIT();
        }
    }

    // ---- store context ----
    #pragma unroll
    for (int dn = 0; dn < 8; dn++) {
        int c = dn * 8 + 2 * tig;
        *(float2*)(ctx + (size_t)qr0 * D_ + c)       = make_float2(O[dn][0], O[dn][1]);
        *(float2*)(ctx + (size_t)(qr0 + 8) * D_ + c) = make_float2(O[dn][2], O[dn][3]);
    }
}

// ---------------------------------------------------------------------------
extern "C" void kernel_launch(void* const* d_in, const int* in_sizes, int n_in,
                              void* d_out, int out_size) {
    const float* Q = (const float*)d_in[0];
    const float* K = (const float*)d_in[1];
    const float* V = (const float*)d_in[2];
    const unsigned char* M = (const unsigned char*)d_in[3];

    cudaFuncSetAttribute(sdpa_kernel, cudaFuncAttributeMaxDynamicSharedMemorySize, 81920);

    pack_kernel<<<(MWORDS + 255) / 256, 256>>>(M);
    prep_kernel<<<5120, 256>>>(K, V);

    dim3 grid(S_ / QT, H_, B_);
    sdpa_kernel<<<grid, NTHR, 81920>>>(Q, (float*)d_out);
}

// round 8
// speedup vs baseline: 1.4244x; 1.0830x over previous
#include <cuda_runtime.h>
#include <cuda_bf16.h>
#include <cstdint>

#define B_    2
#define H_    16
#define S_    2048
#define D_    64
#define BH_   (B_*H_)
#define QT    128
#define KC    64
#define NCH   (S_/KC)
#define NTHR  256
#define SCALEF 0.125f
#define MWORDS (B_ * S_ * S_ / 32)
#define MW_ROW (S_ / 32)
#define RSTRIDE 20              // smem row stride in uint4 (320 B, phase-conflict-free)

// ---------------------------------------------------------------------------
// Globals: fragment-ready K, V^T (bf16 hi/lo interleaved) + packed mask
// ---------------------------------------------------------------------------
__device__ uint4 g_Kf[BH_][S_][16];       // [bh][k-row][kb*4+tig] 16B frags
__device__ uint4 g_Vf[BH_][D_][S_/4];     // [bh][d][sb*4+tig]
__device__ unsigned g_mask_bits[MWORDS];

// ---------------------------------------------------------------------------
// Helpers
// ---------------------------------------------------------------------------
__device__ __forceinline__ void splitf(float x, unsigned short& hi, unsigned short& lo) {
    __nv_bfloat16 h = __float2bfloat16_rn(x);
    hi = __bfloat16_as_ushort(h);
    lo = __bfloat16_as_ushort(__float2bfloat16_rn(x - __bfloat162float(h)));
}
__device__ __forceinline__ void split2(float a, float b, unsigned& hi, unsigned& lo) {
    unsigned short ah, al, bh, bl;
    splitf(a, ah, al); splitf(b, bh, bl);
    hi = (unsigned)ah | ((unsigned)bh << 16);
    lo = (unsigned)al | ((unsigned)bl << 16);
}
__device__ __forceinline__ void mma16816(float* c, const unsigned* a, unsigned b0, unsigned b1) {
    asm volatile(
        "mma.sync.aligned.m16n8k16.row.col.f32.bf16.bf16.f32 "
        "{%0,%1,%2,%3}, {%4,%5,%6,%7}, {%8,%9}, {%0,%1,%2,%3};"
        : "+f"(c[0]), "+f"(c[1]), "+f"(c[2]), "+f"(c[3])
        : "r"(a[0]), "r"(a[1]), "r"(a[2]), "r"(a[3]), "r"(b0), "r"(b1));
}
__device__ __forceinline__ void cpa16(void* smem, const void* g) {
    unsigned s = (unsigned)__cvta_generic_to_shared(smem);
    asm volatile("cp.async.cg.shared.global [%0], [%1], 16;" :: "r"(s), "l"(g));
}
#define CPA_COMMIT() asm volatile("cp.async.commit_group;")
template<int N> __device__ __forceinline__ void cpa_wait() {
    asm volatile("cp.async.wait_group %0;" :: "n"(N));
}
__device__ __forceinline__ unsigned pk4nz(unsigned v) {
    unsigned b = __vminu4(v, 0x01010101u);
    return (b | (b >> 7) | (b >> 14) | (b >> 21)) & 0xFu;
}

// ---------------------------------------------------------------------------
// Merged prep (K frags / V frags / mask pack) — one launch
// blocks [0,4096): K, [4096,5120): V, [5120,6144): mask
// ---------------------------------------------------------------------------
__global__ void prep_pack_kernel(const float* __restrict__ K, const float* __restrict__ V,
                                 const unsigned char* __restrict__ m8) {
    __shared__ float vt[64][65];
    if (blockIdx.x < 4096) {
        int t   = blockIdx.x * 256 + threadIdx.x;
        int bh  = t >> 15;
        int rem = t & 32767;
        int r   = rem >> 4;
        int u   = rem & 15;
        int kb  = u >> 2, tig = u & 3;
        int d0  = kb * 16 + 2 * tig;
        const float* row = K + ((size_t)bh * S_ + r) * D_;
        unsigned h01, l01, h89, l89;
        split2(row[d0],     row[d0 + 1], h01, l01);
        split2(row[d0 + 8], row[d0 + 9], h89, l89);
        g_Kf[bh][r][u] = make_uint4(h01, l01, h89, l89);
    } else if (blockIdx.x < 5120) {
        int blk = blockIdx.x - 4096;
        int bh  = blk >> 5;
        int sc  = blk & 31;
        const float* Vb = V + ((size_t)bh * S_ + sc * 64) * D_;
        for (int i = threadIdx.x; i < 64 * 64; i += 256) {
            int s = i >> 6, d = i & 63;
            vt[s][d] = Vb[s * D_ + d];
        }
        __syncthreads();
        for (int o = threadIdx.x; o < 1024; o += 256) {
            int d = o >> 4, u = o & 15;
            int sbl = u >> 2, tig = u & 3;
            int s0 = sbl * 16 + 2 * tig;
            unsigned h01, l01, h89, l89;
            split2(vt[s0][d],     vt[s0 + 1][d], h01, l01);
            split2(vt[s0 + 8][d], vt[s0 + 9][d], h89, l89);
            g_Vf[bh][d][(sc * 4 + sbl) * 4 + tig] = make_uint4(h01, l01, h89, l89);
        }
    } else {
        const unsigned* mw = (const unsigned*)m8;
        int other = 0;
        for (int i = threadIdx.x; i < 2048; i += 256) {
            unsigned x = mw[i];
            if (x != 0u && x != 1u && x != 0x3F800000u) other = 1;
        }
        int is_u8 = __syncthreads_or(other);
        int w = (blockIdx.x - 5120) * 256 + threadIdx.x;
        if (w >= MWORDS) return;
        unsigned bits = 0;
        if (is_u8) {
            const uint4* p = (const uint4*)(m8 + (size_t)w * 32);
            uint4 u0 = p[0], u1 = p[1];
            bits = pk4nz(u0.x) | (pk4nz(u0.y) << 4) | (pk4nz(u0.z) << 8) | (pk4nz(u0.w) << 12)
                 | (pk4nz(u1.x) << 16) | (pk4nz(u1.y) << 20) | (pk4nz(u1.z) << 24) | (pk4nz(u1.w) << 28);
        } else {
            const uint4* p = (const uint4*)m8 + (size_t)w * 8;
            #pragma unroll
            for (int j = 0; j < 8; j++) {
                uint4 u = p[j];
                bits |= ((unsigned)(u.x != 0u) << (4 * j)) | ((unsigned)(u.y != 0u) << (4 * j + 1))
                      | ((unsigned)(u.z != 0u) << (4 * j + 2)) | ((unsigned)(u.w != 0u) << (4 * j + 3));
            }
        }
        g_mask_bits[w] = bits;
    }
}

// ---------------------------------------------------------------------------
// Chunk prefetch (cp.async, 16B granules)
// ---------------------------------------------------------------------------
__device__ __forceinline__ void pf_k(uint4* kb, int bh, int kc, int tid) {
    const uint4* src = &g_Kf[bh][kc * KC][0];
    #pragma unroll
    for (int i = 0; i < 4; i++) {
        int t = tid + i * NTHR;
        int r = t >> 4, u = t & 15;
        cpa16(kb + r * RSTRIDE + u, src + t);
    }
}
__device__ __forceinline__ void pf_v(uint4* vb, int bh, int kc, int tid) {
    #pragma unroll
    for (int i = 0; i < 4; i++) {
        int t = tid + i * NTHR;
        int d = t >> 4, u = t & 15;
        cpa16(vb + d * RSTRIDE + u, &g_Vf[bh][d][kc * 16 + u]);
    }
}

// ---------------------------------------------------------------------------
// Main kernel: SINGLE sweep. Write e = exp(s*scale) unnormalized, accumulate
// exact l, PV with e; at the end scale O by 1/l and normalize own attn slice.
// ---------------------------------------------------------------------------
__global__ void __launch_bounds__(NTHR, 1)
sdpa_kernel(const float* __restrict__ Q, float* __restrict__ out) {
    extern __shared__ uint4 dsm[];
    uint4* Kb0 = dsm;
    uint4* Kb1 = dsm + 1280;
    uint4* Vb0 = dsm + 2560;
    uint4* Vb1 = dsm + 3840;
    __shared__ float sInv[QT];

    const int tid  = threadIdx.x;
    const int w    = tid >> 5;
    const int lane = tid & 31;
    const int gid  = lane >> 2;
    const int tig  = lane & 3;
    const int b    = blockIdx.z, h = blockIdx.y;
    const int q0   = blockIdx.x * QT;
    const int bh   = b * H_ + h;

    const float* Qb = Q + ((size_t)bh * S_ + q0) * D_;
    float* ctx  = out + ((size_t)bh * S_ + q0) * D_;
    float* attn = out + (size_t)B_ * H_ * S_ * D_ + ((size_t)bh * S_ + q0) * S_;

    const int qr0 = w * 16 + gid;

    // ---- Q fragments from gmem (one-time) ----
    unsigned qhi[4][4], qlo[4][4];
    #pragma unroll
    for (int kb = 0; kb < 4; kb++) {
        int c0 = kb * 16 + 2 * tig;
        float2 a  = *(const float2*)(Qb + (size_t)qr0 * D_ + c0);
        float2 b2 = *(const float2*)(Qb + (size_t)(qr0 + 8) * D_ + c0);
        float2 c  = *(const float2*)(Qb + (size_t)qr0 * D_ + c0 + 8);
        float2 d  = *(const float2*)(Qb + (size_t)(qr0 + 8) * D_ + c0 + 8);
        split2(a.x, a.y, qhi[kb][0], qlo[kb][0]);
        split2(b2.x, b2.y, qhi[kb][1], qlo[kb][1]);
        split2(c.x, c.y, qhi[kb][2], qlo[kb][2]);
        split2(d.x, d.y, qhi[kb][3], qlo[kb][3]);
    }

    const unsigned* mr0 = g_mask_bits + ((size_t)b * S_ + q0 + qr0) * MW_ROW;
    const unsigned* mr1 = mr0 + 8 * MW_ROW;

    float O[8][4];
    #pragma unroll
    for (int dn = 0; dn < 8; dn++)
        O[dn][0] = O[dn][1] = O[dn][2] = O[dn][3] = 0.f;
    float lp0 = 0.f, lp1 = 0.f;   // per-thread partial denominators

    float* arow0 = attn + (size_t)qr0 * S_;
    float* arow1 = attn + (size_t)(qr0 + 8) * S_;

    pf_k(Kb0, bh, 0, tid); pf_v(Vb0, bh, 0, tid); CPA_COMMIT();
    pf_k(Kb1, bh, 1, tid); pf_v(Vb1, bh, 1, tid); CPA_COMMIT();

    for (int kc = 0; kc < NCH; kc++) {
        if (kc + 1 < NCH) cpa_wait<1>(); else cpa_wait<0>();
        __syncthreads();
        const uint4* Kc = (kc & 1) ? Kb1 : Kb0;
        const uint4* Vc = (kc & 1) ? Vb1 : Vb0;

        unsigned pr00 = __ldg(mr0 + 2 * kc), pr01 = __ldg(mr0 + 2 * kc + 1);
        unsigned pr10 = __ldg(mr1 + 2 * kc), pr11 = __ldg(mr1 + 2 * kc + 1);

        unsigned aphi[4][4], aplo[4][4];

        #pragma unroll
        for (int g = 0; g < 2; g++) {
            float s[4][4];
            #pragma unroll
            for (int j = 0; j < 4; j++)
                s[j][0] = s[j][1] = s[j][2] = s[j][3] = 0.f;
            #pragma unroll
            for (int kb = 0; kb < 4; kb++) {
                #pragma unroll
                for (int j = 0; j < 4; j++) {
                    int nb = g * 4 + j;
                    uint4 f = Kc[(nb * 8 + gid) * RSTRIDE + kb * 4 + tig];
                    mma16816(s[j], qhi[kb], f.x, f.z);
                    mma16816(s[j], qlo[kb], f.x, f.z);
                    mma16816(s[j], qhi[kb], f.y, f.w);
                }
            }
            #pragma unroll
            for (int j = 0; j < 4; j++) {
                int nb = g * 4 + j;
                int sh = ((nb & 3) << 3) + 2 * tig;
                unsigned w0 = (nb < 4) ? pr00 : pr01;
                unsigned w1 = (nb < 4) ? pr10 : pr11;
                float e0 = ((w0 >> sh) & 1)       ? 0.f : __expf(s[j][0] * SCALEF);
                float e1 = ((w0 >> (sh + 1)) & 1) ? 0.f : __expf(s[j][1] * SCALEF);
                float e2 = ((w1 >> sh) & 1)       ? 0.f : __expf(s[j][2] * SCALEF);
                float e3 = ((w1 >> (sh + 1)) & 1) ? 0.f : __expf(s[j][3] * SCALEF);
                lp0 += e0 + e1;
                lp1 += e2 + e3;
                int col = kc * KC + nb * 8 + 2 * tig;
                __stcs((float2*)(arow0 + col), make_float2(e0, e1));
                __stcs((float2*)(arow1 + col), make_float2(e2, e3));
                int kb2 = nb >> 1, jj = (nb & 1) << 1;
                split2(e0, e1, aphi[kb2][jj],     aplo[kb2][jj]);
                split2(e2, e3, aphi[kb2][jj + 1], aplo[kb2][jj + 1]);
            }
        }

        // O += E @ V (unnormalized)
        #pragma unroll
        for (int kb2 = 0; kb2 < 4; kb2++) {
            #pragma unroll
            for (int dn = 0; dn < 8; dn++) {
                uint4 f = Vc[(dn * 8 + gid) * RSTRIDE + kb2 * 4 + tig];
                mma16816(O[dn], aphi[kb2], f.x, f.z);
                mma16816(O[dn], aplo[kb2], f.x, f.z);
                mma16816(O[dn], aphi[kb2], f.y, f.w);
            }
        }
        __syncthreads();
        if (kc + 2 < NCH) {
            uint4* kn = (kc & 1) ? Kb1 : Kb0;
            uint4* vn = (kc & 1) ? Vb1 : Vb0;
            pf_k(kn, bh, kc + 2, tid); pf_v(vn, bh, kc + 2, tid); CPA_COMMIT();
        }
    }

    // ---- exact denominators (reduce over tig group) ----
    lp0 += __shfl_xor_sync(0xffffffffu, lp0, 1);
    lp0 += __shfl_xor_sync(0xffffffffu, lp0, 2);
    lp1 += __shfl_xor_sync(0xffffffffu, lp1, 1);
    lp1 += __shfl_xor_sync(0xffffffffu, lp1, 2);
    const float inv0 = 1.0f / lp0;
    const float inv1 = 1.0f / lp1;

    // ---- store normalized context ----
    #pragma unroll
    for (int dn = 0; dn < 8; dn++) {
        int c = dn * 8 + 2 * tig;
        *(float2*)(ctx + (size_t)qr0 * D_ + c)       = make_float2(O[dn][0] * inv0, O[dn][1] * inv0);
        *(float2*)(ctx + (size_t)(qr0 + 8) * D_ + c) = make_float2(O[dn][2] * inv1, O[dn][3] * inv1);
    }

    // ---- publish 1/l to smem, then normalize own attn slice ----
    if (tig == 0) { sInv[qr0] = inv0; sInv[qr0 + 8] = inv1; }
    __syncthreads();

    // 128 rows x 512 float4 per row
    float4* ap = (float4*)attn;
    for (int i = tid; i < QT * (S_ / 4); i += NTHR) {
        int r = i >> 9;
        float m = sInv[r];
        float4 v = __ldcs(ap + i);
        v.x *= m; v.y *= m; v.z *= m; v.w *= m;
        __stcs(ap + i, v);
    }
}

// ---------------------------------------------------------------------------
extern "C" void kernel_launch(void* const* d_in, const int* in_sizes, int n_in,
                              void* d_out, int out_size) {
    const float* Q = (const float*)d_in[0];
    const float* K = (const float*)d_in[1];
    const float* V = (const float*)d_in[2];
    const unsigned char* M = (const unsigned char*)d_in[3];

    cudaFuncSetAttribute(sdpa_kernel, cudaFuncAttributeMaxDynamicSharedMemorySize, 81920);

    prep_pack_kernel<<<6144, 256>>>(K, V, M);

    dim3 grid(S_ / QT, H_, B_);
    sdpa_kernel<<<grid, NTHR, 81920>>>(Q, (float*)d_out);
}

// round 11
// speedup vs baseline: 1.5302x; 1.0743x over previous
#include <cuda_runtime.h>
#include <cuda_bf16.h>
#include <cstdint>

#define B_    2
#define H_    16
#define S_    2048
#define D_    64
#define BH_   (B_*H_)
#define QT    128
#define KC    64
#define NCH   (S_/KC)
#define NTHR  256
#define SCALEF 0.125f
#define MWORDS (B_ * S_ * S_ / 32)
#define MW_ROW (S_ / 32)
#define RSTRIDE 20              // smem row stride in uint4 (320 B, phase-conflict-free)

// ---------------------------------------------------------------------------
// Globals: fragment-ready K, V^T (bf16 hi/lo interleaved) + packed mask
// ---------------------------------------------------------------------------
__device__ uint4 g_Kf[BH_][S_][16];       // [bh][k-row][kb*4+tig] 16B frags
__device__ uint4 g_Vf[BH_][D_][S_/4];     // [bh][d][sb*4+tig]
__device__ unsigned g_mask_bits[MWORDS];

// ---------------------------------------------------------------------------
// Helpers
// ---------------------------------------------------------------------------
// split two floats into packed bf16x2 hi + lo (residual) words: 6 instructions
__device__ __forceinline__ void split2(float a, float b, unsigned& hi, unsigned& lo) {
    unsigned h;
    asm("cvt.rn.bf16x2.f32 %0, %1, %2;" : "=r"(h) : "f"(b), "f"(a));  // {hi16:b, lo16:a}
    float ra = a - __uint_as_float(h << 16);
    float rb = b - __uint_as_float(h & 0xFFFF0000u);
    asm("cvt.rn.bf16x2.f32 %0, %1, %2;" : "=r"(lo) : "f"(rb), "f"(ra));
    hi = h;
}
__device__ __forceinline__ void mma16816(float* c, const unsigned* a, unsigned b0, unsigned b1) {
    asm volatile(
        "mma.sync.aligned.m16n8k16.row.col.f32.bf16.bf16.f32 "
        "{%0,%1,%2,%3}, {%4,%5,%6,%7}, {%8,%9}, {%0,%1,%2,%3};"
        : "+f"(c[0]), "+f"(c[1]), "+f"(c[2]), "+f"(c[3])
        : "r"(a[0]), "r"(a[1]), "r"(a[2]), "r"(a[3]), "r"(b0), "r"(b1));
}
__device__ __forceinline__ void cpa16(void* smem, const void* g) {
    unsigned s = (unsigned)__cvta_generic_to_shared(smem);
    asm volatile("cp.async.cg.shared.global [%0], [%1], 16;" :: "r"(s), "l"(g));
}
#define CPA_COMMIT() asm volatile("cp.async.commit_group;")
template<int N> __device__ __forceinline__ void cpa_wait() {
    asm volatile("cp.async.wait_group %0;" :: "n"(N));
}
__device__ __forceinline__ unsigned pk4nz(unsigned v) {
    unsigned b = __vminu4(v, 0x01010101u);
    return (b | (b >> 7) | (b >> 14) | (b >> 21)) & 0xFu;
}

// ---------------------------------------------------------------------------
// Merged prep (K frags / V frags / mask pack) — one launch
// ---------------------------------------------------------------------------
__global__ void prep_pack_kernel(const float* __restrict__ K, const float* __restrict__ V,
                                 const unsigned char* __restrict__ m8) {
    __shared__ float vt[64][65];
    if (blockIdx.x < 4096) {
        int t   = blockIdx.x * 256 + threadIdx.x;
        int bh  = t >> 15;
        int rem = t & 32767;
        int r   = rem >> 4;
        int u   = rem & 15;
        int kb  = u >> 2, tig = u & 3;
        int d0  = kb * 16 + 2 * tig;
        const float* row = K + ((size_t)bh * S_ + r) * D_;
        unsigned h01, l01, h89, l89;
        split2(row[d0],     row[d0 + 1], h01, l01);
        split2(row[d0 + 8], row[d0 + 9], h89, l89);
        g_Kf[bh][r][u] = make_uint4(h01, l01, h89, l89);
    } else if (blockIdx.x < 5120) {
        int blk = blockIdx.x - 4096;
        int bh  = blk >> 5;
        int sc  = blk & 31;
        const float* Vb = V + ((size_t)bh * S_ + sc * 64) * D_;
        for (int i = threadIdx.x; i < 64 * 64; i += 256) {
            int s = i >> 6, d = i & 63;
            vt[s][d] = Vb[s * D_ + d];
        }
        __syncthreads();
        for (int o = threadIdx.x; o < 1024; o += 256) {
            int d = o >> 4, u = o & 15;
            int sbl = u >> 2, tig = u & 3;
            int s0 = sbl * 16 + 2 * tig;
            unsigned h01, l01, h89, l89;
            split2(vt[s0][d],     vt[s0 + 1][d], h01, l01);
            split2(vt[s0 + 8][d], vt[s0 + 9][d], h89, l89);
            g_Vf[bh][d][(sc * 4 + sbl) * 4 + tig] = make_uint4(h01, l01, h89, l89);
        }
    } else {
        const unsigned* mw = (const unsigned*)m8;
        int other = 0;
        for (int i = threadIdx.x; i < 2048; i += 256) {
            unsigned x = mw[i];
            if (x != 0u && x != 1u && x != 0x3F800000u) other = 1;
        }
        int is_u8 = __syncthreads_or(other);
        int w = (blockIdx.x - 5120) * 256 + threadIdx.x;
        if (w >= MWORDS) return;
        unsigned bits = 0;
        if (is_u8) {
            const uint4* p = (const uint4*)(m8 + (size_t)w * 32);
            uint4 u0 = p[0], u1 = p[1];
            bits = pk4nz(u0.x) | (pk4nz(u0.y) << 4) | (pk4nz(u0.z) << 8) | (pk4nz(u0.w) << 12)
                 | (pk4nz(u1.x) << 16) | (pk4nz(u1.y) << 20) | (pk4nz(u1.z) << 24) | (pk4nz(u1.w) << 28);
        } else {
            const uint4* p = (const uint4*)m8 + (size_t)w * 8;
            #pragma unroll
            for (int j = 0; j < 8; j++) {
                uint4 u = p[j];
                bits |= ((unsigned)(u.x != 0u) << (4 * j)) | ((unsigned)(u.y != 0u) << (4 * j + 1))
                      | ((unsigned)(u.z != 0u) << (4 * j + 2)) | ((unsigned)(u.w != 0u) << (4 * j + 3));
            }
        }
        g_mask_bits[w] = bits;
    }
}

// ---------------------------------------------------------------------------
// Chunk prefetch (cp.async, 16B granules)
// ---------------------------------------------------------------------------
__device__ __forceinline__ void pf_k(uint4* kb, int bh, int kc, int tid) {
    const uint4* src = &g_Kf[bh][kc * KC][0];
    #pragma unroll
    for (int i = 0; i < 4; i++) {
        int t = tid + i * NTHR;
        int r = t >> 4, u = t & 15;
        cpa16(kb + r * RSTRIDE + u, src + t);
    }
}
__device__ __forceinline__ void pf_v(uint4* vb, int bh, int kc, int tid) {
    #pragma unroll
    for (int i = 0; i < 4; i++) {
        int t = tid + i * NTHR;
        int d = t >> 4, u = t & 15;
        cpa16(vb + d * RSTRIDE + u, &g_Vf[bh][d][kc * 16 + u]);
    }
}

// ---------------------------------------------------------------------------
// Main kernel: single sweep, 2 CTAs/SM.
// qlo fragments live in smem (own-thread slots); PV done in two key halves.
// ---------------------------------------------------------------------------
__global__ void __launch_bounds__(NTHR, 2)
sdpa_kernel(const float* __restrict__ Q, float* __restrict__ out) {
    extern __shared__ uint4 dsm[];
    uint4* Kb0 = dsm;
    uint4* Kb1 = dsm + 1280;
    uint4* Vb0 = dsm + 2560;
    uint4* Vb1 = dsm + 3840;
    __shared__ unsigned qloS[NTHR * 20];   // stride 20 words: conflict-free LDS.128
    __shared__ float sInv[QT];

    const int tid  = threadIdx.x;
    const int w    = tid >> 5;
    const int lane = tid & 31;
    const int gid  = lane >> 2;
    const int tig  = lane & 3;
    const int b    = blockIdx.z, h = blockIdx.y;
    const int q0   = blockIdx.x * QT;
    const int bh   = b * H_ + h;

    const float* Qb = Q + ((size_t)bh * S_ + q0) * D_;
    float* ctx  = out + ((size_t)bh * S_ + q0) * D_;
    float* attn = out + (size_t)B_ * H_ * S_ * D_ + ((size_t)bh * S_ + q0) * S_;

    const int qr0 = w * 16 + gid;

    // ---- Q fragments: qhi in regs, qlo in smem (own slot, no sync needed) ----
    unsigned qhi[4][4];
    #pragma unroll
    for (int kb = 0; kb < 4; kb++) {
        int c0 = kb * 16 + 2 * tig;
        float2 a  = *(const float2*)(Qb + (size_t)qr0 * D_ + c0);
        float2 b2 = *(const float2*)(Qb + (size_t)(qr0 + 8) * D_ + c0);
        float2 c  = *(const float2*)(Qb + (size_t)qr0 * D_ + c0 + 8);
        float2 d  = *(const float2*)(Qb + (size_t)(qr0 + 8) * D_ + c0 + 8);
        unsigned lo0, lo1, lo2, lo3;
        split2(a.x, a.y, qhi[kb][0], lo0);
        split2(b2.x, b2.y, qhi[kb][1], lo1);
        split2(c.x, c.y, qhi[kb][2], lo2);
        split2(d.x, d.y, qhi[kb][3], lo3);
        qloS[tid * 20 + kb * 4 + 0] = lo0;
        qloS[tid * 20 + kb * 4 + 1] = lo1;
        qloS[tid * 20 + kb * 4 + 2] = lo2;
        qloS[tid * 20 + kb * 4 + 3] = lo3;
    }

    const unsigned* mr0 = g_mask_bits + ((size_t)b * S_ + q0 + qr0) * MW_ROW;
    const unsigned* mr1 = mr0 + 8 * MW_ROW;

    float O[8][4];
    #pragma unroll
    for (int dn = 0; dn < 8; dn++)
        O[dn][0] = O[dn][1] = O[dn][2] = O[dn][3] = 0.f;
    float lp0 = 0.f, lp1 = 0.f;

    float* arow0 = attn + (size_t)qr0 * S_;
    float* arow1 = attn + (size_t)(qr0 + 8) * S_;

    pf_k(Kb0, bh, 0, tid); pf_v(Vb0, bh, 0, tid); CPA_COMMIT();
    pf_k(Kb1, bh, 1, tid); pf_v(Vb1, bh, 1, tid); CPA_COMMIT();

    for (int kc = 0; kc < NCH; kc++) {
        if (kc + 1 < NCH) cpa_wait<1>(); else cpa_wait<0>();
        __syncthreads();
        const uint4* Kc = (kc & 1) ? Kb1 : Kb0;
        const uint4* Vc = (kc & 1) ? Vb1 : Vb0;

        unsigned pr00 = __ldg(mr0 + 2 * kc), pr01 = __ldg(mr0 + 2 * kc + 1);
        unsigned pr10 = __ldg(mr1 + 2 * kc), pr11 = __ldg(mr1 + 2 * kc + 1);

        #pragma unroll
        for (int g = 0; g < 2; g++) {   // key half: nb = g*4 + j, keys [g*32, g*32+32)
            float s[4][4];
            #pragma unroll
            for (int j = 0; j < 4; j++)
                s[j][0] = s[j][1] = s[j][2] = s[j][3] = 0.f;
            #pragma unroll
            for (int kb = 0; kb < 4; kb++) {
                uint4 qlv = *(const uint4*)(qloS + tid * 20 + kb * 4);
                unsigned ql[4] = {qlv.x, qlv.y, qlv.z, qlv.w};
                #pragma unroll
                for (int j = 0; j < 4; j++) {
                    int nb = g * 4 + j;
                    uint4 f = Kc[(nb * 8 + gid) * RSTRIDE + kb * 4 + tig];
                    mma16816(s[j], qhi[kb], f.x, f.z);
                    mma16816(s[j], ql,      f.x, f.z);
                    mma16816(s[j], qhi[kb], f.y, f.w);
                }
            }

            unsigned aphi[2][4], aplo[2][4];
            #pragma unroll
            for (int j = 0; j < 4; j++) {
                int nb = g * 4 + j;
                int sh = ((nb & 3) << 3) + 2 * tig;
                unsigned w0 = (nb < 4) ? pr00 : pr01;
                unsigned w1 = (nb < 4) ? pr10 : pr11;
                float e0 = ((w0 >> sh) & 1)       ? 0.f : __expf(s[j][0] * SCALEF);
                float e1 = ((w0 >> (sh + 1)) & 1) ? 0.f : __expf(s[j][1] * SCALEF);
                float e2 = ((w1 >> sh) & 1)       ? 0.f : __expf(s[j][2] * SCALEF);
                float e3 = ((w1 >> (sh + 1)) & 1) ? 0.f : __expf(s[j][3] * SCALEF);
                lp0 += e0 + e1;
                lp1 += e2 + e3;
                int col = kc * KC + nb * 8 + 2 * tig;
                __stcs((float2*)(arow0 + col), make_float2(e0, e1));
                __stcs((float2*)(arow1 + col), make_float2(e2, e3));
                int kb2l = j >> 1, jj = (j & 1) << 1;
                split2(e0, e1, aphi[kb2l][jj],     aplo[kb2l][jj]);
                split2(e2, e3, aphi[kb2l][jj + 1], aplo[kb2l][jj + 1]);
            }

            // O += E_half @ V_half
            #pragma unroll
            for (int kb2l = 0; kb2l < 2; kb2l++) {
                int kb2 = g * 2 + kb2l;
                #pragma unroll
                for (int dn = 0; dn < 8; dn++) {
                    uint4 f = Vc[(dn * 8 + gid) * RSTRIDE + kb2 * 4 + tig];
                    mma16816(O[dn], aphi[kb2l], f.x, f.z);
                    mma16816(O[dn], aplo[kb2l], f.x, f.z);
                    mma16816(O[dn], aphi[kb2l], f.y, f.w);
                }
            }
        }

        __syncthreads();
        if (kc + 2 < NCH) {
            uint4* kn = (kc & 1) ? Kb1 : Kb0;
            uint4* vn = (kc & 1) ? Vb1 : Vb0;
            pf_k(kn, bh, kc + 2, tid); pf_v(vn, bh, kc + 2, tid); CPA_COMMIT();
        }
    }

    // ---- exact denominators ----
    lp0 += __shfl_xor_sync(0xffffffffu, lp0, 1);
    lp0 += __shfl_xor_sync(0xffffffffu, lp0, 2);
    lp1 += __shfl_xor_sync(0xffffffffu, lp1, 1);
    lp1 += __shfl_xor_sync(0xffffffffu, lp1, 2);
    const float inv0 = 1.0f / lp0;
    const float inv1 = 1.0f / lp1;

    // ---- store normalized context ----
    #pragma unroll
    for (int dn = 0; dn < 8; dn++) {
        int c = dn * 8 + 2 * tig;
        *(float2*)(ctx + (size_t)qr0 * D_ + c)       = make_float2(O[dn][0] * inv0, O[dn][1] * inv0);
        *(float2*)(ctx + (size_t)(qr0 + 8) * D_ + c) = make_float2(O[dn][2] * inv1, O[dn][3] * inv1);
    }

    // ---- normalize own attn slice ----
    if (tig == 0) { sInv[qr0] = inv0; sInv[qr0 + 8] = inv1; }
    __syncthreads();

    float4* ap = (float4*)attn;
    for (int i = tid; i < QT * (S_ / 4); i += NTHR) {
        int r = i >> 9;
        float m = sInv[r];
        float4 v = __ldcs(ap + i);
        v.x *= m; v.y *= m; v.z *= m; v.w *= m;
        __stcs(ap + i, v);
    }
}

// ---------------------------------------------------------------------------
extern "C" void kernel_launch(void* const* d_in, const int* in_sizes, int n_in,
                              void* d_out, int out_size) {
    const float* Q = (const float*)d_in[0];
    const float* K = (const float*)d_in[1];
    const float* V = (const float*)d_in[2];
    const unsigned char* M = (const unsigned char*)d_in[3];

    cudaFuncSetAttribute(sdpa_kernel, cudaFuncAttributeMaxDynamicSharedMemorySize, 81920);

    prep_pack_kernel<<<6144, 256>>>(K, V, M);

    dim3 grid(S_ / QT, H_, B_);
    sdpa_kernel<<<grid, NTHR, 81920>>>(Q, (float*)d_out);
}

// round 13
// speedup vs baseline: 2.1308x; 1.3925x over previous
#include <cuda_runtime.h>
#include <cuda_fp16.h>
#include <cstdint>

#define B_    2
#define H_    16
#define S_    2048
#define D_    64
#define BH_   (B_*H_)
#define QT    128
#define KC    64
#define NCH   (S_/KC)
#define NTHR  256
#define SCALEF 0.125f
#define MWORDS (B_ * S_ * S_ / 32)
#define MW_ROW (S_ / 32)
#define RS2   20                // smem row stride in uint2 (160 B, conflict-free)

// ---------------------------------------------------------------------------
// Globals: fragment-ready fp16 K, V^T + packed mask
// ---------------------------------------------------------------------------
__device__ uint2 g_Kf[BH_][S_][16];       // 8 MB: [bh][k-row][kb*4+tig] = {d0,d0+1 | d0+8,d0+9}
__device__ uint2 g_Vf[BH_][D_][S_/4];     // 8 MB: [bh][d][(sc*4+kb2)*4+tig]
__device__ unsigned g_mask_bits[MWORDS];

// ---------------------------------------------------------------------------
// Helpers
// ---------------------------------------------------------------------------
// pack two floats into one fp16x2 word: lo16 = a, hi16 = b
__device__ __forceinline__ unsigned pk2h(float a, float b) {
    unsigned r;
    asm("cvt.rn.f16x2.f32 %0, %1, %2;" : "=r"(r) : "f"(b), "f"(a));
    return r;
}
// split two floats into fp16x2 hi + residual-lo words
__device__ __forceinline__ void split2h(float a, float b, unsigned& hi, unsigned& lo) {
    unsigned h = pk2h(a, b);
    __half2 hh = *reinterpret_cast<__half2*>(&h);
    float ra = a - __half2float(__low2half(hh));
    float rb = b - __half2float(__high2half(hh));
    lo = pk2h(ra, rb);
    hi = h;
}
__device__ __forceinline__ void mma16816h(float* c, const unsigned* a, unsigned b0, unsigned b1) {
    asm volatile(
        "mma.sync.aligned.m16n8k16.row.col.f32.f16.f16.f32 "
        "{%0,%1,%2,%3}, {%4,%5,%6,%7}, {%8,%9}, {%0,%1,%2,%3};"
        : "+f"(c[0]), "+f"(c[1]), "+f"(c[2]), "+f"(c[3])
        : "r"(a[0]), "r"(a[1]), "r"(a[2]), "r"(a[3]), "r"(b0), "r"(b1));
}
__device__ __forceinline__ void cpa16(void* smem, const void* g) {
    unsigned s = (unsigned)__cvta_generic_to_shared(smem);
    asm volatile("cp.async.cg.shared.global [%0], [%1], 16;" :: "r"(s), "l"(g));
}
#define CPA_COMMIT() asm volatile("cp.async.commit_group;")
template<int N> __device__ __forceinline__ void cpa_wait() {
    asm volatile("cp.async.wait_group %0;" :: "n"(N));
}
__device__ __forceinline__ unsigned pk4nz(unsigned v) {
    unsigned b = __vminu4(v, 0x01010101u);
    return (b | (b >> 7) | (b >> 14) | (b >> 21)) & 0xFu;
}

// ---------------------------------------------------------------------------
// Merged prep (K frags / V frags / mask pack) — one launch
// blocks [0,4096): K, [4096,5120): V, [5120,6144): mask
// ---------------------------------------------------------------------------
__global__ void prep_pack_kernel(const float* __restrict__ K, const float* __restrict__ V,
                                 const unsigned char* __restrict__ m8) {
    __shared__ float vt[64][65];
    if (blockIdx.x < 4096) {
        int t   = blockIdx.x * 256 + threadIdx.x;
        int bh  = t >> 15;
        int rem = t & 32767;
        int r   = rem >> 4;
        int u   = rem & 15;
        int kb  = u >> 2, tig = u & 3;
        int d0  = kb * 16 + 2 * tig;
        const float* row = K + ((size_t)bh * S_ + r) * D_;
        g_Kf[bh][r][u] = make_uint2(pk2h(row[d0], row[d0 + 1]),
                                    pk2h(row[d0 + 8], row[d0 + 9]));
    } else if (blockIdx.x < 5120) {
        int blk = blockIdx.x - 4096;
        int bh  = blk >> 5;
        int sc  = blk & 31;
        const float* Vb = V + ((size_t)bh * S_ + sc * 64) * D_;
        for (int i = threadIdx.x; i < 64 * 64; i += 256) {
            int s = i >> 6, d = i & 63;
            vt[s][d] = Vb[s * D_ + d];
        }
        __syncthreads();
        for (int o = threadIdx.x; o < 1024; o += 256) {
            int d = o >> 4, u = o & 15;
            int sbl = u >> 2, tig = u & 3;
            int s0 = sbl * 16 + 2 * tig;
            g_Vf[bh][d][(sc * 4 + sbl) * 4 + tig] =
                make_uint2(pk2h(vt[s0][d], vt[s0 + 1][d]),
                           pk2h(vt[s0 + 8][d], vt[s0 + 9][d]));
        }
    } else {
        const unsigned* mw = (const unsigned*)m8;
        int other = 0;
        for (int i = threadIdx.x; i < 2048; i += 256) {
            unsigned x = mw[i];
            if (x != 0u && x != 1u && x != 0x3F800000u) other = 1;
        }
        int is_u8 = __syncthreads_or(other);
        int w = (blockIdx.x - 5120) * 256 + threadIdx.x;
        if (w >= MWORDS) return;
        unsigned bits = 0;
        if (is_u8) {
            const uint4* p = (const uint4*)(m8 + (size_t)w * 32);
            uint4 u0 = p[0], u1 = p[1];
            bits = pk4nz(u0.x) | (pk4nz(u0.y) << 4) | (pk4nz(u0.z) << 8) | (pk4nz(u0.w) << 12)
                 | (pk4nz(u1.x) << 16) | (pk4nz(u1.y) << 20) | (pk4nz(u1.z) << 24) | (pk4nz(u1.w) << 28);
        } else {
            const uint4* p = (const uint4*)m8 + (size_t)w * 8;
            #pragma unroll
            for (int j = 0; j < 8; j++) {
                uint4 u = p[j];
                bits |= ((unsigned)(u.x != 0u) << (4 * j)) | ((unsigned)(u.y != 0u) << (4 * j + 1))
                      | ((unsigned)(u.z != 0u) << (4 * j + 2)) | ((unsigned)(u.w != 0u) << (4 * j + 3));
            }
        }
        g_mask_bits[w] = bits;
    }
}

// ---------------------------------------------------------------------------
// Chunk prefetch: 64 rows x 128 B payload into stride-160B smem rows.
// 512 granules of 16 B per buffer -> 2 cp.async per thread.
// ---------------------------------------------------------------------------
__device__ __forceinline__ void pf_k(uint2* kb, int bh, int kc, int tid) {
    const uint2* src = &g_Kf[bh][kc * KC][0];
    #pragma unroll
    for (int i = 0; i < 2; i++) {
        int idx = tid + i * NTHR;
        int r = idx >> 3, u = idx & 7;
        cpa16(kb + r * RS2 + u * 2, src + idx * 2);
    }
}
__device__ __forceinline__ void pf_v(uint2* vb, int bh, int kc, int tid) {
    #pragma unroll
    for (int i = 0; i < 2; i++) {
        int idx = tid + i * NTHR;
        int d = idx >> 3, u = idx & 7;
        cpa16(vb + d * RS2 + u * 2, &g_Vf[bh][d][kc * 16 + u * 2]);
    }
}

// ---------------------------------------------------------------------------
// Main kernel: single sweep, fp16 2-split operands, 2 CTAs/SM.
// ---------------------------------------------------------------------------
__global__ void __launch_bounds__(NTHR, 2)
sdpa_kernel(const float* __restrict__ Q, float* __restrict__ out) {
    extern __shared__ uint2 dsm[];
    uint2* Kb0 = dsm;
    uint2* Kb1 = dsm + 1280;
    uint2* Vb0 = dsm + 2560;
    uint2* Vb1 = dsm + 3840;
    __shared__ __align__(16) unsigned qloS[NTHR * 20];
    __shared__ float sInv[QT];

    const int tid  = threadIdx.x;
    const int w    = tid >> 5;
    const int lane = tid & 31;
    const int gid  = lane >> 2;
    const int tig  = lane & 3;
    const int b    = blockIdx.z, h = blockIdx.y;
    const int q0   = blockIdx.x * QT;
    const int bh   = b * H_ + h;

    const float* Qb = Q + ((size_t)bh * S_ + q0) * D_;
    float* ctx  = out + ((size_t)bh * S_ + q0) * D_;
    float* attn = out + (size_t)B_ * H_ * S_ * D_ + ((size_t)bh * S_ + q0) * S_;

    const int qr0 = w * 16 + gid;

    // ---- Q fragments: qhi in regs, qlo in smem (own slot) ----
    unsigned qhi[4][4];
    #pragma unroll
    for (int kb = 0; kb < 4; kb++) {
        int c0 = kb * 16 + 2 * tig;
        float2 a  = *(const float2*)(Qb + (size_t)qr0 * D_ + c0);
        float2 b2 = *(const float2*)(Qb + (size_t)(qr0 + 8) * D_ + c0);
        float2 c  = *(const float2*)(Qb + (size_t)qr0 * D_ + c0 + 8);
        float2 d  = *(const float2*)(Qb + (size_t)(qr0 + 8) * D_ + c0 + 8);
        unsigned lo0, lo1, lo2, lo3;
        split2h(a.x, a.y, qhi[kb][0], lo0);
        split2h(b2.x, b2.y, qhi[kb][1], lo1);
        split2h(c.x, c.y, qhi[kb][2], lo2);
        split2h(d.x, d.y, qhi[kb][3], lo3);
        qloS[tid * 20 + kb * 4 + 0] = lo0;
        qloS[tid * 20 + kb * 4 + 1] = lo1;
        qloS[tid * 20 + kb * 4 + 2] = lo2;
        qloS[tid * 20 + kb * 4 + 3] = lo3;
    }

    const unsigned* mr0 = g_mask_bits + ((size_t)b * S_ + q0 + qr0) * MW_ROW;
    const unsigned* mr1 = mr0 + 8 * MW_ROW;

    float O[8][4];
    #pragma unroll
    for (int dn = 0; dn < 8; dn++)
        O[dn][0] = O[dn][1] = O[dn][2] = O[dn][3] = 0.f;
    float lp0 = 0.f, lp1 = 0.f;

    float* arow0 = attn + (size_t)qr0 * S_;
    float* arow1 = attn + (size_t)(qr0 + 8) * S_;

    pf_k(Kb0, bh, 0, tid); pf_v(Vb0, bh, 0, tid); CPA_COMMIT();
    pf_k(Kb1, bh, 1, tid); pf_v(Vb1, bh, 1, tid); CPA_COMMIT();

    for (int kc = 0; kc < NCH; kc++) {
        if (kc + 1 < NCH) cpa_wait<1>(); else cpa_wait<0>();
        __syncthreads();
        const uint2* Kc = (kc & 1) ? Kb1 : Kb0;
        const uint2* Vc = (kc & 1) ? Vb1 : Vb0;

        unsigned pr00 = __ldg(mr0 + 2 * kc), pr01 = __ldg(mr0 + 2 * kc + 1);
        unsigned pr10 = __ldg(mr1 + 2 * kc), pr11 = __ldg(mr1 + 2 * kc + 1);

        #pragma unroll
        for (int g = 0; g < 2; g++) {   // key half: nb = g*4 + j
            float s[4][4];
            #pragma unroll
            for (int j = 0; j < 4; j++)
                s[j][0] = s[j][1] = s[j][2] = s[j][3] = 0.f;
            #pragma unroll
            for (int kb = 0; kb < 4; kb++) {
                uint4 qlv = *(const uint4*)(qloS + tid * 20 + kb * 4);
                unsigned ql[4] = {qlv.x, qlv.y, qlv.z, qlv.w};
                #pragma unroll
                for (int j = 0; j < 4; j++) {
                    int nb = g * 4 + j;
                    uint2 f = Kc[(nb * 8 + gid) * RS2 + kb * 4 + tig];
                    mma16816h(s[j], qhi[kb], f.x, f.y);
                    mma16816h(s[j], ql,      f.x, f.y);
                }
            }

            unsigned aphi[2][4], aplo[2][4];
            #pragma unroll
            for (int j = 0; j < 4; j++) {
                int nb = g * 4 + j;
                int sh = ((nb & 3) << 3) + 2 * tig;
                unsigned w0 = (nb < 4) ? pr00 : pr01;
                unsigned w1 = (nb < 4) ? pr10 : pr11;
                float e0 = ((w0 >> sh) & 1)       ? 0.f : __expf(s[j][0] * SCALEF);
                float e1 = ((w0 >> (sh + 1)) & 1) ? 0.f : __expf(s[j][1] * SCALEF);
                float e2 = ((w1 >> sh) & 1)       ? 0.f : __expf(s[j][2] * SCALEF);
                float e3 = ((w1 >> (sh + 1)) & 1) ? 0.f : __expf(s[j][3] * SCALEF);
                lp0 += e0 + e1;
                lp1 += e2 + e3;
                int col = kc * KC + nb * 8 + 2 * tig;
                __stcs((float2*)(arow0 + col), make_float2(e0, e1));
                __stcs((float2*)(arow1 + col), make_float2(e2, e3));
                int kb2l = j >> 1, jj = (j & 1) << 1;
                split2h(e0, e1, aphi[kb2l][jj],     aplo[kb2l][jj]);
                split2h(e2, e3, aphi[kb2l][jj + 1], aplo[kb2l][jj + 1]);
            }

            // O += E_half @ V_half
            #pragma unroll
            for (int kb2l = 0; kb2l < 2; kb2l++) {
                int kb2 = g * 2 + kb2l;
                #pragma unroll
                for (int dn = 0; dn < 8; dn++) {
                    uint2 f = Vc[(dn * 8 + gid) * RS2 + kb2 * 4 + tig];
                    mma16816h(O[dn], aphi[kb2l], f.x, f.y);
                    mma16816h(O[dn], aplo[kb2l], f.x, f.y);
                }
            }
        }

        __syncthreads();
        if (kc + 2 < NCH) {
            uint2* kn = (kc & 1) ? Kb1 : Kb0;
            uint2* vn = (kc & 1) ? Vb1 : Vb0;
            pf_k(kn, bh, kc + 2, tid); pf_v(vn, bh, kc + 2, tid); CPA_COMMIT();
        }
    }

    // ---- exact denominators ----
    lp0 += __shfl_xor_sync(0xffffffffu, lp0, 1);
    lp0 += __shfl_xor_sync(0xffffffffu, lp0, 2);
    lp1 += __shfl_xor_sync(0xffffffffu, lp1, 1);
    lp1 += __shfl_xor_sync(0xffffffffu, lp1, 2);
    const float inv0 = 1.0f / lp0;
    const float inv1 = 1.0f / lp1;

    // ---- store normalized context ----
    #pragma unroll
    for (int dn = 0; dn < 8; dn++) {
        int c = dn * 8 + 2 * tig;
        *(float2*)(ctx + (size_t)qr0 * D_ + c)       = make_float2(O[dn][0] * inv0, O[dn][1] * inv0);
        *(float2*)(ctx + (size_t)(qr0 + 8) * D_ + c) = make_float2(O[dn][2] * inv1, O[dn][3] * inv1);
    }

    // ---- normalize own attn slice ----
    if (tig == 0) { sInv[qr0] = inv0; sInv[qr0 + 8] = inv1; }
    __syncthreads();

    float4* ap = (float4*)attn;
    for (int i = tid; i < QT * (S_ / 4); i += NTHR) {
        int r = i >> 9;
        float m = sInv[r];
        float4 v = __ldcs(ap + i);
        v.x *= m; v.y *= m; v.z *= m; v.w *= m;
        __stcs(ap + i, v);
    }
}

// ---------------------------------------------------------------------------
extern "C" void kernel_launch(void* const* d_in, const int* in_sizes, int n_in,
                              void* d_out, int out_size) {
    const float* Q = (const float*)d_in[0];
    const float* K = (const float*)d_in[1];
    const float* V = (const float*)d_in[2];
    const unsigned char* M = (const unsigned char*)d_in[3];

    cudaFuncSetAttribute(sdpa_kernel, cudaFuncAttributeMaxDynamicSharedMemorySize, 40960);

    prep_pack_kernel<<<6144, 256>>>(K, V, M);

    dim3 grid(S_ / QT, H_, B_);
    sdpa_kernel<<<grid, NTHR, 40960>>>(Q, (float*)d_out);
}